// round 7
// baseline (speedup 1.0000x reference)
#include <cuda_runtime.h>
#include <math.h>
#include <stdint.h>

// L = 1 collapses the Mamba scan: h = dBu, y = dt*xin*(Bm.Cm) + D*xin, A_log dead.
#define BB      512
#define DMODEL  512
#define DSTATE  128
#define DINNER  1024
#define DTRANK  32
#define HIDDEN  256
#define PAD     320              // padded xdbl row (288 -> 320, multiple of 64)
#define NCTA    148              // 1 CTA/SM, guaranteed co-resident

// -------- scratch (no allocations allowed; __device__ globals) --------
__device__ float g_xin  [BB*DINNER];
__device__ float g_zsil [BB*DINNER];
__device__ float g_xdblp[4*BB*PAD];      // x_proj split-K partial planes (padded)
__device__ float g_opart[4*BB*DMODEL];   // out_proj split-K partial planes
__device__ float g_y    [BB*DINNER];
__device__ float g_h1   [BB*HIDDEN];

// -------- software grid barrier (replay-safe: gen monotonic, cnt self-resets)
__device__ unsigned g_cnt = 0;
__device__ unsigned g_gen = 0;

__device__ __forceinline__ void grid_sync()
{
    __threadfence();
    __syncthreads();
    if (threadIdx.x == 0) {
        unsigned gen = atomicAdd(&g_gen, 0u);   // read BEFORE arrival
        __threadfence();
        if (atomicAdd(&g_cnt, 1u) == NCTA - 1) {
            g_cnt = 0;
            __threadfence();
            atomicAdd(&g_gen, 1u);
        } else {
            while (atomicAdd(&g_gen, 0u) == gen) { __nanosleep(64); }
        }
    }
    __syncthreads();
}

__device__ __forceinline__ float siluf(float x) { return x / (1.f + __expf(-x)); }

__device__ __forceinline__ void mma_tf32(float c[4],
                                         unsigned a0, unsigned a1, unsigned a2, unsigned a3,
                                         unsigned b0, unsigned b1)
{
    asm volatile(
        "mma.sync.aligned.m16n8k8.row.col.f32.tf32.tf32.f32 "
        "{%0,%1,%2,%3}, {%4,%5,%6,%7}, {%8,%9}, {%0,%1,%2,%3};"
        : "+f"(c[0]), "+f"(c[1]), "+f"(c[2]), "+f"(c[3])
        : "r"(a0), "r"(a1), "r"(a2), "r"(a3), "r"(b0), "r"(b1));
}

__device__ __forceinline__ void cp16(void* smem, const void* gmem)
{
    unsigned sa = (unsigned)__cvta_generic_to_shared(smem);
    asm volatile("cp.async.cg.shared.global [%0], [%1], 16;" :: "r"(sa), "l"(gmem));
}

__device__ __forceinline__ void ldsm_x4(unsigned& r0, unsigned& r1,
                                        unsigned& r2, unsigned& r3, const void* p)
{
    unsigned a = (unsigned)__cvta_generic_to_shared(p);
    asm volatile("ldmatrix.sync.aligned.m8n8.x4.shared.b16 {%0,%1,%2,%3}, [%4];"
                 : "=r"(r0), "=r"(r1), "=r"(r2), "=r"(r3) : "r"(a));
}

// ---------------------------------------------------------------------
// One 64x64 C-tile: C = A[M,K] @ W[N,K]^T via tf32 mma, fp32 accum.
// 256 thr = 8 warps (2m x 4n), warp tile 32x16, MT=2 x NT=2 chains.
// 3-stage cp.async (wait_group 1) + ldmatrix fragments (both proven).
// SUMA>1: A tile = sum of SUMA planes (stride aplane), sync float4 loads.
// W rows clamped to wmax (harmless dup reads; padded outputs never read).
// MODE 0: store  1: +bias leaky  2: in_proj split  3: bc+softplus+y
// ---------------------------------------------------------------------
template<int MODE, int SUMA>
__device__ void gemm_tile(float* __restrict__ smem,
                          int m0, int n0,
                          const float* __restrict__ A, int lda, long aplane,
                          const float* __restrict__ W, int ldw, int wmax,
                          float* __restrict__ C, int ldc, int K,
                          const float* __restrict__ aux0,
                          const float* __restrict__ aux1,
                          float* __restrict__ out2)
{
    constexpr int SROW = 36;                 // row stride (floats): 16B-aligned, conflict-free
    constexpr int TILE = 64 * SROW;
    float* As  = smem;                       // 3 stages x 64 rows
    float* Ws  = smem + 3 * TILE;
    float* sbc = smem + 6 * TILE;

    const int tid  = threadIdx.x;
    const int lane = tid & 31;
    const int wid  = tid >> 5;               // 0..7
    const int wm   = wid & 1;                // 2 warps along m (32 rows each)
    const int wn   = wid >> 1;               // 4 warps along n (16 cols each)
    const int g    = lane >> 2;
    const int t    = lane & 3;
    const int arow = tid >> 3;               // 0..31
    const int acol = (tid & 7) * 4;

    // MODE3: bc[r] = dot(Bm, Cm) of the SUMA-summed planes (A = g_xdblp, lda = PAD)
    if (MODE == 3) {
        #pragma unroll
        for (int rr = 0; rr < 8; ++rr) {
            const int r = wid * 8 + rr;
            const long base = (long)(m0 + r) * lda;
            float v = 0.f;
            #pragma unroll
            for (int i = 0; i < DSTATE / 32; ++i) {
                float a = 0.f, b = 0.f;
                #pragma unroll
                for (int p = 0; p < SUMA; ++p) {
                    a += A[p*aplane + base + DTRANK + lane + 32*i];
                    b += A[p*aplane + base + DTRANK + DSTATE + lane + 32*i];
                }
                v += a * b;
            }
            #pragma unroll
            for (int o = 16; o > 0; o >>= 1) v += __shfl_xor_sync(0xFFFFFFFFu, v, o);
            if (lane == 0) sbc[r] = v;
        }
    }

    auto load = [&](int kt, int st) {
        const int k0 = kt * 32;
        float* as = As + st * TILE;
        float* ws = Ws + st * TILE;
        if (SUMA == 1) {
            #pragma unroll
            for (int r = 0; r < 2; ++r)
                cp16(as + (arow + 32*r)*SROW + acol,
                     A + (long)(m0 + arow + 32*r)*lda + k0 + acol);
        } else {
            #pragma unroll
            for (int r = 0; r < 2; ++r) {
                const long base = (long)(m0 + arow + 32*r)*lda + k0 + acol;
                float4 s = make_float4(0.f, 0.f, 0.f, 0.f);
                #pragma unroll
                for (int p = 0; p < SUMA; ++p) {
                    float4 v = *reinterpret_cast<const float4*>(&A[p*aplane + base]);
                    s.x += v.x; s.y += v.y; s.z += v.z; s.w += v.w;
                }
                *reinterpret_cast<float4*>(as + (arow + 32*r)*SROW + acol) = s;
            }
        }
        #pragma unroll
        for (int r = 0; r < 2; ++r) {
            int wr = n0 + arow + 32*r;
            if (wr > wmax) wr = wmax;        // clamp (dup read; padded cols never read)
            cp16(ws + (arow + 32*r)*SROW + acol, W + (long)wr*ldw + k0 + acol);
        }
    };

    float acc[2][2][4] = {};
    const int NK = K / 32;

    load(0, 0);
    asm volatile("cp.async.commit_group;");
    if (NK > 1) {
        load(1, 1);
        asm volatile("cp.async.commit_group;");
    }

    for (int it = 0; it < NK; ++it) {
        if (it + 1 < NK) asm volatile("cp.async.wait_group 1;");
        else             asm volatile("cp.async.wait_group 0;");
        __syncthreads();                     // stage it visible; compute(it-1) done

        if (it + 2 < NK) {
            load(it + 2, (it + 2) % 3);
            asm volatile("cp.async.commit_group;");
        }

        float* as = As + (it % 3) * TILE;
        float* ws = Ws + (it % 3) * TILE;
        #pragma unroll
        for (int ks = 0; ks < 4; ++ks) {
            unsigned b00, b10, b01, b11;
            ldsm_x4(b00, b10, b01, b11,
                    ws + (wn*16 + ((lane >> 4) << 3) + (lane & 7))*SROW
                       + ks*8 + 4*((lane >> 3) & 1));
            #pragma unroll
            for (int mt = 0; mt < 2; ++mt) {
                unsigned a0, a1, a2, a3;
                ldsm_x4(a0, a1, a2, a3,
                        as + (wm*32 + mt*16 + (lane & 15))*SROW + ks*8 + 4*(lane >> 4));
                mma_tf32(acc[mt][0], a0, a1, a2, a3, b00, b10);
                mma_tf32(acc[mt][1], a0, a1, a2, a3, b01, b11);
            }
        }
    }
    __syncthreads();                         // smem free for next tile / epilogue-safe

    // ---- epilogue ----
    #pragma unroll
    for (int mt = 0; mt < 2; ++mt) {
        #pragma unroll
        for (int nt = 0; nt < 2; ++nt) {
            const int nb = n0 + wn*16 + nt*8 + 2*t;
            #pragma unroll
            for (int half = 0; half < 2; ++half) {
                const int m = m0 + wm*32 + mt*16 + g + 8*half;
                float v0 = acc[mt][nt][2*half + 0];
                float v1 = acc[mt][nt][2*half + 1];
                if (MODE == 0) {
                    *reinterpret_cast<float2*>(&C[(long)m*ldc + nb]) = make_float2(v0, v1);
                } else if (MODE == 1) {
                    v0 += aux0[nb]; v1 += aux0[nb + 1];
                    v0 = (v0 >= 0.f) ? v0 : 0.1f * v0;
                    v1 = (v1 >= 0.f) ? v1 : 0.1f * v1;
                    *reinterpret_cast<float2*>(&C[(long)m*ldc + nb]) = make_float2(v0, v1);
                } else if (MODE == 2) {
                    if (n0 < DINNER) {
                        float c0 = aux0[nb]     + aux1[2*nb + 1]     * v0;
                        float c1 = aux0[nb + 1] + aux1[2*(nb+1) + 1] * v1;
                        *reinterpret_cast<float2*>(&C[(long)m*DINNER + nb]) =
                            make_float2(siluf(c0), siluf(c1));
                    } else {
                        *reinterpret_cast<float2*>(&out2[(long)m*DINNER + nb - DINNER]) =
                            make_float2(siluf(v0), siluf(v1));
                    }
                } else { // MODE 3
                    v0 += aux0[nb]; v1 += aux0[nb + 1];
                    float dt0 = (v0 > 20.f) ? v0 : log1pf(__expf(v0));
                    float dt1 = (v1 > 20.f) ? v1 : log1pf(__expf(v1));
                    float2 xv = *reinterpret_cast<const float2*>(&g_xin [(long)m*DINNER + nb]);
                    float2 zv = *reinterpret_cast<const float2*>(&g_zsil[(long)m*DINNER + nb]);
                    float bc  = sbc[m - m0];
                    float y0 = (dt0 * xv.x * bc + aux1[nb]     * xv.x) * zv.x;
                    float y1 = (dt1 * xv.y * bc + aux1[nb + 1] * xv.y) * zv.y;
                    *reinterpret_cast<float2*>(&C[(long)m*DINNER + nb]) = make_float2(y0, y1);
                }
            }
        }
    }
}

// ---------------------------------------------------------------------
// Persistent fused kernel: all 6 stages, grid barriers in between.
// ---------------------------------------------------------------------
__global__ void __launch_bounds__(256)
fused_kernel(const float* __restrict__ x,
             const float* __restrict__ in_proj_w,
             const float* __restrict__ conv_w,
             const float* __restrict__ conv_b,
             const float* __restrict__ x_proj_w,
             const float* __restrict__ dt_proj_w,
             const float* __restrict__ dt_proj_b,
             const float* __restrict__ Dp,
             const float* __restrict__ out_projw,
             const float* __restrict__ fc1_w,
             const float* __restrict__ fc1_b,
             const float* __restrict__ fc5_w,
             const float* __restrict__ fc5_b,
             float* __restrict__ out)
{
    extern __shared__ float smem[];
    const int bid = blockIdx.x;
    const long XP = (long)BB * PAD;
    const long OP = (long)BB * DMODEL;

    // S1: in_proj (M=512, N=2048, K=512) + conv + silu split -> xin, zsil  [256 tiles]
    for (int tile = bid; tile < 256; tile += NCTA) {
        const int mb = tile >> 5, nb = tile & 31;
        gemm_tile<2, 1>(smem, mb*64, nb*64, x, DMODEL, 0,
                        in_proj_w, DMODEL, 2*DINNER - 1,
                        g_xin, DINNER, DMODEL, conv_b, conv_w, g_zsil);
    }
    grid_sync();

    // S2: x_proj split-K x4 (K-slice 256) -> padded xdbl partials          [160 tiles]
    for (int tile = bid; tile < 160; tile += NCTA) {
        const int z = tile & 3, r = tile >> 2;
        const int nb = r % 5, mb = r / 5;
        gemm_tile<0, 1>(smem, mb*64, nb*64, g_xin + z*256, DINNER, 0,
                        x_proj_w + z*256, DINNER, 287,
                        g_xdblp + (long)z*XP, PAD, 256, nullptr, nullptr, nullptr);
    }
    grid_sync();

    // S3: dt_proj (K=32) on summed planes + inline bc + y                  [128 tiles]
    for (int tile = bid; tile < 128; tile += NCTA) {
        const int mb = tile >> 4, nb = tile & 15;
        gemm_tile<3, 4>(smem, mb*64, nb*64, g_xdblp, PAD, XP,
                        dt_proj_w, DTRANK, DINNER - 1,
                        g_y, DINNER, DTRANK, dt_proj_b, Dp, nullptr);
    }
    grid_sync();

    // S4: out_proj split-K x4 -> opart partial planes                      [256 tiles]
    for (int tile = bid; tile < 256; tile += NCTA) {
        const int z = tile & 3, r = tile >> 2;
        const int nb = r & 7, mb = r >> 3;
        gemm_tile<0, 1>(smem, mb*64, nb*64, g_y + z*256, DINNER, 0,
                        out_projw + z*256, DINNER, DMODEL - 1,
                        g_opart + (long)z*OP, DMODEL, 256, nullptr, nullptr, nullptr);
    }
    grid_sync();

    // S5: fc1 on summed partial planes (SUMA=4) + bias + leaky -> h1       [32 tiles]
    for (int tile = bid; tile < 32; tile += NCTA) {
        const int mb = tile >> 2, nb = tile & 3;
        gemm_tile<1, 4>(smem, mb*64, nb*64, g_opart, DMODEL, OP,
                        fc1_w, DMODEL, HIDDEN - 1,
                        g_h1, HIDDEN, DMODEL, fc1_b, nullptr, nullptr);
    }
    grid_sync();

    // S6: fc5 + sigmoid -> out (B,1)
    {
        const int tid  = threadIdx.x;
        const int lane = tid & 31;
        const int wid  = tid >> 5;
        float* red = smem;                   // smem free now
        for (int b = bid; b < BB; b += NCTA) {
            float v = g_h1[b*HIDDEN + tid] * fc5_w[tid];
            #pragma unroll
            for (int o = 16; o > 0; o >>= 1) v += __shfl_xor_sync(0xFFFFFFFFu, v, o);
            if (lane == 0) red[wid] = v;
            __syncthreads();
            if (tid == 0) {
                float s = fc5_b[0];
                #pragma unroll
                for (int i = 0; i < 8; i++) s += red[i];
                out[b] = 1.f / (1.f + __expf(-s));
            }
            __syncthreads();
        }
    }
}

extern "C" void kernel_launch(void* const* d_in, const int* in_sizes, int n_in,
                              void* d_out, int out_size)
{
    const float* x         = (const float*)d_in[0];
    const float* in_proj_w = (const float*)d_in[1];
    const float* conv_w    = (const float*)d_in[2];
    const float* conv_b    = (const float*)d_in[3];
    const float* x_proj_w  = (const float*)d_in[4];
    const float* dt_proj_w = (const float*)d_in[5];
    const float* dt_proj_b = (const float*)d_in[6];
    // d_in[7] = A_log: dead (h0 = 0, L = 1)
    const float* Dp        = (const float*)d_in[8];
    const float* out_projw = (const float*)d_in[9];
    const float* fc1_w     = (const float*)d_in[10];
    const float* fc1_b     = (const float*)d_in[11];
    const float* fc5_w     = (const float*)d_in[12];
    const float* fc5_b     = (const float*)d_in[13];
    float* out = (float*)d_out;

    // 3-stage A(64) + W(64) tiles at stride 36 + sbc(64): 55,552 bytes
    const int SMEM_BYTES = (6 * 64 * 36 + 64) * (int)sizeof(float);
    cudaFuncSetAttribute(fused_kernel,
                         cudaFuncAttributeMaxDynamicSharedMemorySize, SMEM_BYTES);

    fused_kernel<<<NCTA, 256, SMEM_BYTES>>>(x, in_proj_w, conv_w, conv_b,
                                            x_proj_w, dt_proj_w, dt_proj_b, Dp,
                                            out_projw, fc1_w, fc1_b, fc5_w, fc5_b,
                                            out);
}

// round 8
// speedup vs baseline: 1.0069x; 1.0069x over previous
#include <cuda_runtime.h>
#include <math.h>
#include <stdint.h>

// L = 1 collapses the Mamba scan: h = dBu, y = dt*xin*(Bm.Cm) + D*xin, A_log dead.
#define BB      512
#define DMODEL  512
#define DSTATE  128
#define DINNER  1024
#define DTRANK  32
#define HIDDEN  256
#define XDBL_W  (DTRANK + 2*DSTATE)   // 288
#define SPLK    8                     // split-K factor for the K=1024 GEMMs

// -------- scratch (no allocations allowed; __device__ globals) --------
__device__ float g_xin  [BB*DINNER];
__device__ float g_zsil [BB*DINNER];
__device__ float g_xdblp[SPLK*BB*XDBL_W];  // x_proj split-K partial planes
__device__ float g_opart[SPLK*BB*DMODEL];  // out_proj split-K partial planes
__device__ float g_y    [BB*DINNER];
__device__ float g_h1   [BB*HIDDEN];

__device__ __forceinline__ float siluf(float x) { return x / (1.f + __expf(-x)); }

__device__ __forceinline__ void mma_tf32(float c[4],
                                         unsigned a0, unsigned a1, unsigned a2, unsigned a3,
                                         unsigned b0, unsigned b1)
{
    asm volatile(
        "mma.sync.aligned.m16n8k8.row.col.f32.tf32.tf32.f32 "
        "{%0,%1,%2,%3}, {%4,%5,%6,%7}, {%8,%9}, {%0,%1,%2,%3};"
        : "+f"(c[0]), "+f"(c[1]), "+f"(c[2]), "+f"(c[3])
        : "r"(a0), "r"(a1), "r"(a2), "r"(a3), "r"(b0), "r"(b1));
}

__device__ __forceinline__ void cp16(void* smem, const void* gmem)
{
    unsigned sa = (unsigned)__cvta_generic_to_shared(smem);
    asm volatile("cp.async.cg.shared.global [%0], [%1], 16;" :: "r"(sa), "l"(gmem));
}

__device__ __forceinline__ void ldsm_x4(unsigned& r0, unsigned& r1,
                                        unsigned& r2, unsigned& r3, const void* p)
{
    unsigned a = (unsigned)__cvta_generic_to_shared(p);
    asm volatile("ldmatrix.sync.aligned.m8n8.x4.shared.b16 {%0,%1,%2,%3}, [%4];"
                 : "=r"(r0), "=r"(r1), "=r"(r2), "=r"(r3) : "r"(a));
}

// ---------------------------------------------------------------------
// tf32 GEMM: 3-stage cp.async (wait_group 1) + ldmatrix fragments.
// BM=64, BN=32, BK=32, 128 thr = 4 warps (2m x 2n), warp tile 32x16.
// SPLITZ>1: blockIdx.z = K-slice; C -> partial plane z (stride cplane).
// SUMA>1  : A tile = sum of SUMA planes (stride aplane; sync float4 loads).
// MODE 0: store  MODE 1: +bias leaky  MODE 2: in_proj split  MODE 3: dt+y
// ---------------------------------------------------------------------
template<int MODE, int SPLITZ, int SUMA>
__global__ void __launch_bounds__(128)
gemm_v8(const float* __restrict__ A, int lda, long aplane,
        const float* __restrict__ W, int ldw,
        float* __restrict__ C, int N, int K, long cplane,
        const float* __restrict__ aux0,
        const float* __restrict__ aux1,
        float* __restrict__ out2)
{
    constexpr int BM  = 64;
    constexpr int BN  = 32;
    constexpr int BK  = 32;
    constexpr int LDS = BK + 4;        // 36 floats: 16B-aligned rows, LDSM conflict-free
    constexpr int NST = 3;

    __shared__ float As[NST][BM][LDS];
    __shared__ float Ws[NST][BN][LDS];
    __shared__ float sbc[BM];

    const int tid  = threadIdx.x;
    const int lane = tid & 31;
    const int wid  = tid >> 5;
    const int wm   = wid & 1;
    const int wn   = wid >> 1;
    const int g    = lane >> 2;
    const int t    = lane & 3;
    const int m0   = blockIdx.y * BM;
    const int n0   = blockIdx.x * BN;

    const int z = (SPLITZ > 1) ? blockIdx.z : 0;
    const float* Az = A + (long)z * K;
    const float* Wz = W + (long)z * K;
    float* Cz = C + ((SPLITZ > 1) ? (long)z * cplane : 0L);

    const int arow = tid >> 3;         // 0..15
    const int acol = (tid & 7) * 4;

    // ldmatrix per-thread offsets (r6-proven layout)
    const int a_r = (lane & 15);                 // + wm*32 + mt*16
    const int a_c = 4 * (lane >> 4);             // + ks*8
    const int b_r = wn * 16 + ((lane >> 4) << 3) + (lane & 7);
    const int b_c = 4 * ((lane >> 3) & 1);       // + ks*8

    // MODE3: bc[r] = dot(Bm, Cm) of summed planes (A = g_xdblp, lda = XDBL_W)
    if (MODE == 3) {
        #pragma unroll
        for (int rr = 0; rr < 16; ++rr) {
            const int r = wid * 16 + rr;
            const long base = (long)(m0 + r) * lda;
            float v = 0.f;
            #pragma unroll
            for (int i = 0; i < DSTATE / 32; ++i) {
                float a = 0.f, b = 0.f;
                #pragma unroll
                for (int p = 0; p < SUMA; ++p) {
                    a += A[p*aplane + base + DTRANK + lane + 32*i];
                    b += A[p*aplane + base + DTRANK + DSTATE + lane + 32*i];
                }
                v += a * b;
            }
            #pragma unroll
            for (int o = 16; o > 0; o >>= 1) v += __shfl_xor_sync(0xFFFFFFFFu, v, o);
            if (lane == 0) sbc[r] = v;
        }
    }

    const int NK = K / BK;

    auto load_tiles = [&](int kt, int buf) {
        const int k0 = kt * BK;
        if (SUMA == 1) {
            #pragma unroll
            for (int r = 0; r < 4; ++r)
                cp16(&As[buf][arow + 16*r][acol], &Az[(long)(m0 + arow + 16*r) * lda + k0 + acol]);
        } else {
            #pragma unroll
            for (int r = 0; r < 4; ++r) {
                const long base = (long)(m0 + arow + 16*r) * lda + k0 + acol;
                float4 s = make_float4(0.f, 0.f, 0.f, 0.f);
                #pragma unroll
                for (int p = 0; p < SUMA; ++p) {
                    float4 v = *reinterpret_cast<const float4*>(&A[p*aplane + base]);
                    s.x += v.x; s.y += v.y; s.z += v.z; s.w += v.w;
                }
                *reinterpret_cast<float4*>(&As[buf][arow + 16*r][acol]) = s;
            }
        }
        #pragma unroll
        for (int r = 0; r < 2; ++r)
            cp16(&Ws[buf][arow + 16*r][acol], &Wz[(long)(n0 + arow + 16*r) * ldw + k0 + acol]);
    };

    float acc[2][2][4] = {};

    load_tiles(0, 0);
    asm volatile("cp.async.commit_group;");
    if (NK > 1) {
        load_tiles(1, 1);
        asm volatile("cp.async.commit_group;");
    }

    for (int it = 0; it < NK; ++it) {
        if (it + 1 < NK) asm volatile("cp.async.wait_group 1;");
        else             asm volatile("cp.async.wait_group 0;");
        __syncthreads();               // stage 'it' visible; compute(it-1) done by all

        if (it + 2 < NK) {             // overwrites buffer freed at it-1
            load_tiles(it + 2, (it + 2) % NST);
            asm volatile("cp.async.commit_group;");
        }

        const int buf = it % NST;
        #pragma unroll
        for (int ks = 0; ks < BK / 8; ++ks) {
            unsigned b00, b10, b01, b11;
            ldsm_x4(b00, b10, b01, b11, &Ws[buf][b_r][ks*8 + b_c]);
            #pragma unroll
            for (int mt = 0; mt < 2; ++mt) {
                unsigned a0, a1, a2, a3;
                ldsm_x4(a0, a1, a2, a3, &As[buf][wm*32 + mt*16 + a_r][ks*8 + a_c]);
                mma_tf32(acc[mt][0], a0, a1, a2, a3, b00, b10);
                mma_tf32(acc[mt][1], a0, a1, a2, a3, b01, b11);
            }
        }
    }

    // ---- epilogue ----
    #pragma unroll
    for (int mt = 0; mt < 2; ++mt) {
        #pragma unroll
        for (int nt = 0; nt < 2; ++nt) {
            const int nb = n0 + wn * 16 + nt * 8 + 2 * t;
            #pragma unroll
            for (int half = 0; half < 2; ++half) {
                const int m = m0 + wm * 32 + mt * 16 + g + 8 * half;
                float v0 = acc[mt][nt][2*half + 0];
                float v1 = acc[mt][nt][2*half + 1];
                if (MODE == 0) {
                    *reinterpret_cast<float2*>(&Cz[(long)m * N + nb]) = make_float2(v0, v1);
                } else if (MODE == 1) {
                    v0 += aux0[nb]; v1 += aux0[nb + 1];
                    v0 = (v0 >= 0.f) ? v0 : 0.1f * v0;
                    v1 = (v1 >= 0.f) ? v1 : 0.1f * v1;
                    *reinterpret_cast<float2*>(&Cz[(long)m * N + nb]) = make_float2(v0, v1);
                } else if (MODE == 2) {
                    if (n0 < DINNER) {
                        float c0 = aux0[nb]     + aux1[2*nb + 1]     * v0;
                        float c1 = aux0[nb + 1] + aux1[2*(nb+1) + 1] * v1;
                        *reinterpret_cast<float2*>(&Cz[(long)m * DINNER + nb]) =
                            make_float2(siluf(c0), siluf(c1));
                    } else {
                        *reinterpret_cast<float2*>(&out2[(long)m * DINNER + nb - DINNER]) =
                            make_float2(siluf(v0), siluf(v1));
                    }
                } else { // MODE 3
                    v0 += aux0[nb]; v1 += aux0[nb + 1];
                    float dt0 = (v0 > 20.f) ? v0 : log1pf(__expf(v0));
                    float dt1 = (v1 > 20.f) ? v1 : log1pf(__expf(v1));
                    float2 xv = *reinterpret_cast<const float2*>(&g_xin [(long)m * DINNER + nb]);
                    float2 zv = *reinterpret_cast<const float2*>(&g_zsil[(long)m * DINNER + nb]);
                    float bc  = sbc[m - m0];
                    float y0 = (dt0 * xv.x * bc + aux1[nb]     * xv.x) * zv.x;
                    float y1 = (dt1 * xv.y * bc + aux1[nb + 1] * xv.y) * zv.y;
                    *reinterpret_cast<float2*>(&Cz[(long)m * DINNER + nb]) = make_float2(y0, y1);
                }
            }
        }
    }
}

// out[b] = sigmoid( dot(h1[b], fc5_w) + fc5_b )
__global__ void fc5_kernel(const float* __restrict__ w,
                           const float* __restrict__ bias,
                           float* __restrict__ out)
{
    const int b = blockIdx.x;
    const int t = threadIdx.x;  // 256
    float v = g_h1[b * HIDDEN + t] * w[t];
    #pragma unroll
    for (int o = 16; o > 0; o >>= 1) v += __shfl_xor_sync(0xFFFFFFFFu, v, o);
    __shared__ float ws[8];
    if ((t & 31) == 0) ws[t >> 5] = v;
    __syncthreads();
    if (t == 0) {
        float s = bias[0];
        #pragma unroll
        for (int i = 0; i < 8; i++) s += ws[i];
        out[b] = 1.f / (1.f + __expf(-s));
    }
}

extern "C" void kernel_launch(void* const* d_in, const int* in_sizes, int n_in,
                              void* d_out, int out_size)
{
    const float* x         = (const float*)d_in[0];
    const float* in_proj_w = (const float*)d_in[1];
    const float* conv_w    = (const float*)d_in[2];
    const float* conv_b    = (const float*)d_in[3];
    const float* x_proj_w  = (const float*)d_in[4];
    const float* dt_proj_w = (const float*)d_in[5];
    const float* dt_proj_b = (const float*)d_in[6];
    // d_in[7] = A_log: dead (h0 = 0, L = 1)
    const float* Dp        = (const float*)d_in[8];
    const float* out_projw = (const float*)d_in[9];
    const float* fc1_w     = (const float*)d_in[10];
    const float* fc1_b     = (const float*)d_in[11];
    const float* fc5_w     = (const float*)d_in[12];
    const float* fc5_b     = (const float*)d_in[13];
    float* out = (float*)d_out;

    float *xin, *zsil, *xdblp, *opart, *y, *h1;
    cudaGetSymbolAddress((void**)&xin,   g_xin);
    cudaGetSymbolAddress((void**)&zsil,  g_zsil);
    cudaGetSymbolAddress((void**)&xdblp, g_xdblp);
    cudaGetSymbolAddress((void**)&opart, g_opart);
    cudaGetSymbolAddress((void**)&y,     g_y);
    cudaGetSymbolAddress((void**)&h1,    g_h1);

    const dim3 blk(128);
    const long XP = (long)BB * XDBL_W;   // xdbl plane
    const long OP = (long)BB * DMODEL;   // out1 plane

    // 1. in_proj (N=2048,K=512) + conv + silu split            [512 CTAs]
    gemm_v8<2,1,1><<<dim3(64, 8), blk>>>(x, DMODEL, 0, in_proj_w, DMODEL,
                                         xin, 2*DINNER, DMODEL, 0, conv_b, conv_w, zsil);
    // 2. x_proj split-K x8 (slices K=128) -> xdbl partials     [576 CTAs]
    gemm_v8<0,SPLK,1><<<dim3(9, 8, SPLK), blk>>>(xin, DINNER, 0, x_proj_w, DINNER,
                                                 xdblp, XDBL_W, DINNER/SPLK, XP,
                                                 nullptr, nullptr, nullptr);
    // 3. dt_proj (K=32) on summed planes + bc + y              [256 CTAs]
    gemm_v8<3,1,SPLK><<<dim3(32, 8), blk>>>(xdblp, XDBL_W, XP, dt_proj_w, DTRANK,
                                            y, DINNER, DTRANK, 0, dt_proj_b, Dp, nullptr);
    // 4. out_proj split-K x8 -> out1 partials                  [1024 CTAs]
    gemm_v8<0,SPLK,1><<<dim3(16, 8, SPLK), blk>>>(y, DINNER, 0, out_projw, DINNER,
                                                  opart, DMODEL, DINNER/SPLK, OP,
                                                  nullptr, nullptr, nullptr);
    // 5. fc1 on summed partial planes (SUMA=8) + leaky         [64 CTAs]
    gemm_v8<1,1,SPLK><<<dim3(8, 8), blk>>>(opart, DMODEL, OP, fc1_w, DMODEL,
                                           h1, HIDDEN, DMODEL, 0, fc1_b, nullptr, nullptr);
    // 6. fc5 + sigmoid -> out (B,1)
    fc5_kernel<<<BB, 256>>>(fc5_w, fc5_b, out);
}

// round 9
// speedup vs baseline: 1.6698x; 1.6584x over previous
#include <cuda_runtime.h>
#include <cuda_bf16.h>
#include <math.h>
#include <stdint.h>

// L = 1 collapses the Mamba scan: h = dBu, y = dt*xin*(Bm.Cm) + D*xin, A_log dead.
#define BB      512
#define DMODEL  512
#define DSTATE  128
#define DINNER  1024
#define DTRANK  32
#define HIDDEN  256
#define XDBL_W  (DTRANK + 2*DSTATE)   // 288
#define SPLK    4

// -------- scratch (no allocations; __device__ globals) --------
// bf16 weight / activation mirrors
__device__ __nv_bfloat16 b_x   [BB*DMODEL];
__device__ __nv_bfloat16 b_win [2*DINNER*DMODEL];
__device__ __nv_bfloat16 b_wxp [XDBL_W*DINNER];
__device__ __nv_bfloat16 b_wdt [DINNER*DTRANK];
__device__ __nv_bfloat16 b_wop [DMODEL*DINNER];
__device__ __nv_bfloat16 b_wfc1[HIDDEN*DMODEL];
__device__ __nv_bfloat16 g_xinb [BB*DINNER];
__device__ __nv_bfloat16 g_zsilb[BB*DINNER];
__device__ __nv_bfloat16 g_yb   [BB*DINNER];
__device__ __nv_bfloat16 g_o1b  [BB*DMODEL];
// fp32 intermediates
__device__ float g_xdblp[SPLK*BB*XDBL_W];
__device__ float g_opart[SPLK*BB*DMODEL];
__device__ float g_h1   [BB*HIDDEN];

__device__ __forceinline__ float siluf(float x) { return x / (1.f + __expf(-x)); }

__device__ __forceinline__ unsigned short bfb(float f) {
    __nv_bfloat16 h = __float2bfloat16(f);
    return *reinterpret_cast<unsigned short*>(&h);
}
__device__ __forceinline__ float bff(__nv_bfloat16 h) { return __bfloat162float(h); }

__device__ __forceinline__ void mma_bf16(float c[4],
                                         unsigned a0, unsigned a1, unsigned a2, unsigned a3,
                                         unsigned b0, unsigned b1)
{
    asm volatile(
        "mma.sync.aligned.m16n8k16.row.col.f32.bf16.bf16.f32 "
        "{%0,%1,%2,%3}, {%4,%5,%6,%7}, {%8,%9}, {%0,%1,%2,%3};"
        : "+f"(c[0]), "+f"(c[1]), "+f"(c[2]), "+f"(c[3])
        : "r"(a0), "r"(a1), "r"(a2), "r"(a3), "r"(b0), "r"(b1));
}

__device__ __forceinline__ void cp16(void* smem, const void* gmem)
{
    unsigned sa = (unsigned)__cvta_generic_to_shared(smem);
    asm volatile("cp.async.cg.shared.global [%0], [%1], 16;" :: "r"(sa), "l"(gmem));
}

__device__ __forceinline__ void ldsm_x4(unsigned& r0, unsigned& r1,
                                        unsigned& r2, unsigned& r3, const void* p)
{
    unsigned a = (unsigned)__cvta_generic_to_shared(p);
    asm volatile("ldmatrix.sync.aligned.m8n8.x4.shared.b16 {%0,%1,%2,%3}, [%4];"
                 : "=r"(r0), "=r"(r1), "=r"(r2), "=r"(r3) : "r"(a));
}

// ---------------------------------------------------------------------
// bf16 GEMM: C = A[M,K] @ W[N,K]^T, m16n8k16 mma, fp32 accum.
// BM=64, BN=64, BK=32. 256 thr = 8 warps (2m x 4n), warp tile 32x16.
// 3-stage cp.async (wait_group 1) + ldmatrix x4 fragments.
// SPLITZ>1: blockIdx.z = K-slice; C -> fp32 partial plane z.
// SUMA>1  : A = sum of SUMA fp32 planes, converted bf16 (sync; only K=32 user)
// MODE 0: fp32 store (+n<N guard)  1: +bias leaky -> fp32
// MODE 2: in_proj split -> bf16 xin/zsil   3: bc+softplus+y -> bf16 y
// ---------------------------------------------------------------------
template<int MODE, int SPLITZ, int SUMA>
__global__ void __launch_bounds__(256)
gemm_bf(const void* __restrict__ Av, int lda, long aplane,
        const __nv_bfloat16* __restrict__ W, int ldw, int wclamp,
        void* __restrict__ Cv, int N, int K, long cplane,
        const float* __restrict__ aux0,
        const float* __restrict__ aux1,
        __nv_bfloat16* __restrict__ out2)
{
    constexpr int LDSB = 40;           // bf16 units: 80B rows, 16B-aligned, LDSM conflict-free
    __shared__ __align__(16) __nv_bfloat16 As[3][64][LDSB];
    __shared__ __align__(16) __nv_bfloat16 Ws[3][64][LDSB];
    __shared__ float sbc[64];

    const int tid  = threadIdx.x;
    const int lane = tid & 31;
    const int wid  = tid >> 5;         // 0..7
    const int wm   = wid & 1;          // 2 warps along m
    const int wn   = wid >> 1;         // 4 warps along n
    const int g    = lane >> 2;
    const int t    = lane & 3;
    const int m0   = blockIdx.y * 64;
    const int n0   = blockIdx.x * 64;

    const int z = (SPLITZ > 1) ? blockIdx.z : 0;
    const __nv_bfloat16* Ab = (const __nv_bfloat16*)Av + (long)z * K;  // SUMA==1 path
    const float*         Af = (const float*)Av;                        // SUMA>1 path
    const __nv_bfloat16* Wz = W + (long)z * K;
    float* Cf = (float*)Cv + ((SPLITZ > 1) ? (long)z * cplane : 0L);

    const int lrow = tid >> 2;         // 0..63
    const int lc8  = (tid & 3) * 8;    // bf16 col: 0,8,16,24

    // ldmatrix per-thread offsets (r6-proven pattern, 16B chunk = 8 bf16)
    const int a_r = lane & 15;                          // + wm*32 + mt*16
    const int a_c = (lane >> 4) * 8;                    // + ks*16
    const int b_r = wn * 16 + ((lane >> 4) << 3) + (lane & 7);
    const int b_c = ((lane >> 3) & 1) * 8;              // + ks*16

    // MODE3: bc[r] = dot(Bm, Cm) of SUMA-summed fp32 planes (lda = XDBL_W)
    if (MODE == 3) {
        #pragma unroll
        for (int rr = 0; rr < 8; ++rr) {
            const int r = wid * 8 + rr;
            const long base = (long)(m0 + r) * lda;
            float v = 0.f;
            #pragma unroll
            for (int i = 0; i < DSTATE / 32; ++i) {
                float a = 0.f, b = 0.f;
                #pragma unroll
                for (int p = 0; p < SUMA; ++p) {
                    a += Af[p*aplane + base + DTRANK + lane + 32*i];
                    b += Af[p*aplane + base + DTRANK + DSTATE + lane + 32*i];
                }
                v += a * b;
            }
            #pragma unroll
            for (int o = 16; o > 0; o >>= 1) v += __shfl_xor_sync(0xFFFFFFFFu, v, o);
            if (lane == 0) sbc[r] = v;
        }
    }

    const int NK = K / 32;

    auto load_tiles = [&](int kt, int buf) {
        const int k0 = kt * 32;
        if (SUMA == 1) {
            cp16(&As[buf][lrow][lc8], &Ab[(long)(m0 + lrow) * lda + k0 + lc8]);
        } else {
            // sum SUMA fp32 planes -> 8 bf16 (only used with NK==1, k0==0)
            const long base = (long)(m0 + lrow) * lda + k0 + lc8;
            float s[8] = {};
            #pragma unroll
            for (int p = 0; p < SUMA; ++p) {
                float4 v0 = *reinterpret_cast<const float4*>(&Af[p*aplane + base]);
                float4 v1 = *reinterpret_cast<const float4*>(&Af[p*aplane + base + 4]);
                s[0]+=v0.x; s[1]+=v0.y; s[2]+=v0.z; s[3]+=v0.w;
                s[4]+=v1.x; s[5]+=v1.y; s[6]+=v1.z; s[7]+=v1.w;
            }
            uint4 u;
            u.x = bfb(s[0]) | ((unsigned)bfb(s[1]) << 16);
            u.y = bfb(s[2]) | ((unsigned)bfb(s[3]) << 16);
            u.z = bfb(s[4]) | ((unsigned)bfb(s[5]) << 16);
            u.w = bfb(s[6]) | ((unsigned)bfb(s[7]) << 16);
            *reinterpret_cast<uint4*>(&As[buf][lrow][lc8]) = u;
        }
        int wr = n0 + lrow;
        if (wr > wclamp) wr = wclamp;   // dup reads; padded outputs never stored
        cp16(&Ws[buf][lrow][lc8], &Wz[(long)wr * ldw + k0 + lc8]);
    };

    float acc[2][2][4] = {};

    load_tiles(0, 0);
    asm volatile("cp.async.commit_group;");
    if (NK > 1) {
        load_tiles(1, 1);
        asm volatile("cp.async.commit_group;");
    }

    for (int it = 0; it < NK; ++it) {
        if (it + 1 < NK) asm volatile("cp.async.wait_group 1;");
        else             asm volatile("cp.async.wait_group 0;");
        __syncthreads();

        if (it + 2 < NK) {
            load_tiles(it + 2, (it + 2) % 3);
            asm volatile("cp.async.commit_group;");
        }

        const int buf = it % 3;
        #pragma unroll
        for (int ks = 0; ks < 2; ++ks) {     // two k16 steps per BK=32
            unsigned b00, b10, b01, b11;
            ldsm_x4(b00, b10, b01, b11, &Ws[buf][b_r][ks*16 + b_c]);
            #pragma unroll
            for (int mt = 0; mt < 2; ++mt) {
                unsigned a0, a1, a2, a3;
                ldsm_x4(a0, a1, a2, a3, &As[buf][wm*32 + mt*16 + a_r][ks*16 + a_c]);
                mma_bf16(acc[mt][0], a0, a1, a2, a3, b00, b10);
                mma_bf16(acc[mt][1], a0, a1, a2, a3, b01, b11);
            }
        }
    }

    // ---- epilogue: c0:(m,nb) c1:(m,nb+1) c2:(m+8,nb) c3:(m+8,nb+1) ----
    #pragma unroll
    for (int mt = 0; mt < 2; ++mt) {
        #pragma unroll
        for (int nt = 0; nt < 2; ++nt) {
            const int nb = n0 + wn*16 + nt*8 + 2*t;
            #pragma unroll
            for (int half = 0; half < 2; ++half) {
                const int m = m0 + wm*32 + mt*16 + g + 8*half;
                float v0 = acc[mt][nt][2*half + 0];
                float v1 = acc[mt][nt][2*half + 1];
                if (MODE == 0) {
                    if (nb < N - 1)
                        *reinterpret_cast<float2*>(&Cf[(long)m*N + nb]) = make_float2(v0, v1);
                } else if (MODE == 1) {
                    v0 += aux0[nb]; v1 += aux0[nb + 1];
                    v0 = (v0 >= 0.f) ? v0 : 0.1f * v0;
                    v1 = (v1 >= 0.f) ? v1 : 0.1f * v1;
                    *reinterpret_cast<float2*>(&Cf[(long)m*N + nb]) = make_float2(v0, v1);
                } else if (MODE == 2) {
                    unsigned pr;
                    if (n0 < DINNER) {      // uniform per CTA (1024 % 64 == 0)
                        float c0 = aux0[nb]     + aux1[2*nb + 1]     * v0;
                        float c1 = aux0[nb + 1] + aux1[2*(nb+1) + 1] * v1;
                        pr = bfb(siluf(c0)) | ((unsigned)bfb(siluf(c1)) << 16);
                        *reinterpret_cast<unsigned*>(&g_xinb[(long)m*DINNER + nb]) = pr;
                    } else {
                        pr = bfb(siluf(v0)) | ((unsigned)bfb(siluf(v1)) << 16);
                        *reinterpret_cast<unsigned*>(&out2[(long)m*DINNER + nb - DINNER]) = pr;
                    }
                } else { // MODE 3
                    v0 += aux0[nb]; v1 += aux0[nb + 1];
                    float dt0 = (v0 > 20.f) ? v0 : log1pf(__expf(v0));
                    float dt1 = (v1 > 20.f) ? v1 : log1pf(__expf(v1));
                    __nv_bfloat162 xv = *reinterpret_cast<const __nv_bfloat162*>(&g_xinb [(long)m*DINNER + nb]);
                    __nv_bfloat162 zv = *reinterpret_cast<const __nv_bfloat162*>(&g_zsilb[(long)m*DINNER + nb]);
                    float bc = sbc[m - m0];
                    float y0 = (dt0 * bff(xv.x) * bc + aux1[nb]     * bff(xv.x)) * bff(zv.x);
                    float y1 = (dt1 * bff(xv.y) * bc + aux1[nb + 1] * bff(xv.y)) * bff(zv.y);
                    unsigned pr = bfb(y0) | ((unsigned)bfb(y1) << 16);
                    *reinterpret_cast<unsigned*>(&g_yb[(long)m*DINNER + nb]) = pr;
                }
            }
        }
    }
}

// ---------------- pre-pass: fp32 -> bf16 for weights + x ----------------
__global__ void convert_kernel(const float* __restrict__ x,
                               const float* __restrict__ win,
                               const float* __restrict__ wxp,
                               const float* __restrict__ wdt,
                               const float* __restrict__ wop,
                               const float* __restrict__ wfc1)
{
    // segment sizes in float4 units
    constexpr int S0 = BB*DMODEL/4;            // x        65536
    constexpr int S1 = 2*DINNER*DMODEL/4;      // in_proj 262144
    constexpr int S2 = XDBL_W*DINNER/4;        // x_proj   73728
    constexpr int S3 = DINNER*DTRANK/4;        // dt        8192
    constexpr int S4 = DMODEL*DINNER/4;        // out_proj 131072
    constexpr int S5 = HIDDEN*DMODEL/4;        // fc1       32768
    constexpr int TOT = S0+S1+S2+S3+S4+S5;

    for (int i = blockIdx.x * blockDim.x + threadIdx.x; i < TOT;
         i += gridDim.x * blockDim.x) {
        const float* src; __nv_bfloat16* dst; int j = i;
        if      (j < S0)            { src = x;    dst = b_x; }
        else if ((j -= S0) < S1)    { src = win;  dst = b_win; }
        else if ((j -= S1) < S2)    { src = wxp;  dst = b_wxp; }
        else if ((j -= S2) < S3)    { src = wdt;  dst = b_wdt; }
        else if ((j -= S3) < S4)    { src = wop;  dst = b_wop; }
        else                        { j -= S4;    src = wfc1; dst = b_wfc1; }
        float4 v = reinterpret_cast<const float4*>(src)[j];
        uint2 u;
        u.x = bfb(v.x) | ((unsigned)bfb(v.y) << 16);
        u.y = bfb(v.z) | ((unsigned)bfb(v.w) << 16);
        reinterpret_cast<uint2*>(dst)[j] = u;
    }
}

// out1_b (bf16) = sum of SPLK fp32 out_proj planes
__global__ void reduce_kernel()
{
    const int i = blockIdx.x * blockDim.x + threadIdx.x;   // 65536 float4s
    const float4* p = reinterpret_cast<const float4*>(g_opart);
    const long plane4 = (long)BB * DMODEL / 4;
    float4 s = p[i];
    #pragma unroll
    for (int z = 1; z < SPLK; ++z) {
        float4 v = p[i + z*plane4];
        s.x += v.x; s.y += v.y; s.z += v.z; s.w += v.w;
    }
    uint2 u;
    u.x = bfb(s.x) | ((unsigned)bfb(s.y) << 16);
    u.y = bfb(s.z) | ((unsigned)bfb(s.w) << 16);
    reinterpret_cast<uint2*>(g_o1b)[i] = u;
}

// out[b] = sigmoid( dot(h1[b], fc5_w) + fc5_b )
__global__ void fc5_kernel(const float* __restrict__ w,
                           const float* __restrict__ bias,
                           float* __restrict__ out)
{
    const int b = blockIdx.x;
    const int t = threadIdx.x;  // 256
    float v = g_h1[b * HIDDEN + t] * w[t];
    #pragma unroll
    for (int o = 16; o > 0; o >>= 1) v += __shfl_xor_sync(0xFFFFFFFFu, v, o);
    __shared__ float ws[8];
    if ((t & 31) == 0) ws[t >> 5] = v;
    __syncthreads();
    if (t == 0) {
        float s = bias[0];
        #pragma unroll
        for (int i = 0; i < 8; i++) s += ws[i];
        out[b] = 1.f / (1.f + __expf(-s));
    }
}

extern "C" void kernel_launch(void* const* d_in, const int* in_sizes, int n_in,
                              void* d_out, int out_size)
{
    const float* x         = (const float*)d_in[0];
    const float* in_proj_w = (const float*)d_in[1];
    const float* conv_w    = (const float*)d_in[2];
    const float* conv_b    = (const float*)d_in[3];
    const float* x_proj_w  = (const float*)d_in[4];
    const float* dt_proj_w = (const float*)d_in[5];
    const float* dt_proj_b = (const float*)d_in[6];
    // d_in[7] = A_log: dead (h0 = 0, L = 1)
    const float* Dp        = (const float*)d_in[8];
    const float* out_projw = (const float*)d_in[9];
    const float* fc1_w     = (const float*)d_in[10];
    const float* fc1_b     = (const float*)d_in[11];
    const float* fc5_w     = (const float*)d_in[12];
    const float* fc5_b     = (const float*)d_in[13];
    float* out = (float*)d_out;

    void *xb, *wib, *wxb, *wdb, *wob, *wfb, *xinb, *zsb, *yb, *o1b, *xdp, *opr, *h1;
    cudaGetSymbolAddress(&xb,  b_x);    cudaGetSymbolAddress(&wib, b_win);
    cudaGetSymbolAddress(&wxb, b_wxp);  cudaGetSymbolAddress(&wdb, b_wdt);
    cudaGetSymbolAddress(&wob, b_wop);  cudaGetSymbolAddress(&wfb, b_wfc1);
    cudaGetSymbolAddress(&xinb, g_xinb); cudaGetSymbolAddress(&zsb, g_zsilb);
    cudaGetSymbolAddress(&yb,  g_yb);   cudaGetSymbolAddress(&o1b, g_o1b);
    cudaGetSymbolAddress(&xdp, g_xdblp); cudaGetSymbolAddress(&opr, g_opart);
    cudaGetSymbolAddress(&h1,  g_h1);

    const long XP = (long)BB * XDBL_W;
    const long OP = (long)BB * DMODEL;
    const dim3 blk(256);

    // 0. fp32 -> bf16 pre-pass (weights + x)
    convert_kernel<<<1024, 256>>>(x, in_proj_w, x_proj_w, dt_proj_w, out_projw, fc1_w);
    // 1. in_proj (N=2048,K=512) + conv + silu split -> bf16 xin,zsil   [256 CTAs]
    gemm_bf<2,1,1><<<dim3(32, 8), blk>>>(xb, DMODEL, 0,
        (const __nv_bfloat16*)wib, DMODEL, 2*DINNER - 1,
        nullptr, 2*DINNER, DMODEL, 0, conv_b, conv_w, (__nv_bfloat16*)zsb);
    // 2. x_proj split-K x4 (K=256 slices) -> fp32 partials             [160 CTAs]
    gemm_bf<0,SPLK,1><<<dim3(5, 8, SPLK), blk>>>(xinb, DINNER, 0,
        (const __nv_bfloat16*)wxb, DINNER, XDBL_W - 1,
        xdp, XDBL_W, DINNER/SPLK, XP, nullptr, nullptr, nullptr);
    // 3. dt_proj (K=32) on summed planes + bc + y -> bf16 y            [128 CTAs]
    gemm_bf<3,1,SPLK><<<dim3(16, 8), blk>>>(xdp, XDBL_W, XP,
        (const __nv_bfloat16*)wdb, DTRANK, DINNER - 1,
        nullptr, DINNER, DTRANK, 0, dt_proj_b, Dp, nullptr);
    // 4. out_proj split-K x4 -> fp32 partials                          [256 CTAs]
    gemm_bf<0,SPLK,1><<<dim3(8, 8, SPLK), blk>>>(yb, DINNER, 0,
        (const __nv_bfloat16*)wob, DINNER, DMODEL - 1,
        opr, DMODEL, DINNER/SPLK, OP, nullptr, nullptr, nullptr);
    // 5. out1_b = bf16(sum of planes)
    reduce_kernel<<<256, 256>>>();
    // 6. fc1 (N=256,K=512) + bias + leaky -> fp32 h1                   [32 CTAs]
    gemm_bf<1,1,1><<<dim3(4, 8), blk>>>(o1b, DMODEL, 0,
        (const __nv_bfloat16*)wfb, DMODEL, HIDDEN - 1,
        h1, HIDDEN, DMODEL, 0, fc1_b, nullptr, nullptr);
    // 7. fc5 + sigmoid -> out (B,1)
    fc5_kernel<<<BB, 256>>>(fc5_w, fc5_b, out);
}

// round 11
// speedup vs baseline: 1.7352x; 1.0391x over previous
#include <cuda_runtime.h>
#include <cuda_bf16.h>
#include <math.h>
#include <stdint.h>

// L = 1 collapses the Mamba scan: h = dBu, y = dt*xin*(Bm.Cm) + D*xin, A_log dead.
#define BB      512
#define DMODEL  512
#define DSTATE  128
#define DINNER  1024
#define DTRANK  32
#define HIDDEN  256
#define XDBL_W  (DTRANK + 2*DSTATE)   // 288
#define SPLK    4

// -------- scratch (no allocations; __device__ globals) --------
__device__ __nv_bfloat16 b_x   [BB*DMODEL];
__device__ __nv_bfloat16 b_win [2*DINNER*DMODEL];
__device__ __nv_bfloat16 b_wxp [XDBL_W*DINNER];
__device__ __nv_bfloat16 b_wdt [DINNER*DTRANK];
__device__ __nv_bfloat16 b_wop [DMODEL*DINNER];
__device__ __nv_bfloat16 b_wfc1[HIDDEN*DMODEL];
__device__ __nv_bfloat16 g_xinb [BB*DINNER];
__device__ __nv_bfloat16 g_zsilb[BB*DINNER];
__device__ __nv_bfloat16 g_dtb  [BB*DTRANK];   // summed dt activations (bf16)
__device__ __nv_bfloat16 g_yb   [BB*DINNER];
__device__ __nv_bfloat16 g_o1b  [BB*DMODEL];
__device__ float g_xdblp[SPLK*BB*XDBL_W];      // x_proj split-K fp32 partials
__device__ float g_opart[SPLK*BB*DMODEL];      // out_proj split-K fp32 partials
__device__ float g_bc   [BB];                  // dot(Bm, Cm) per row
__device__ float g_h1   [BB*HIDDEN];

__device__ __forceinline__ float siluf(float x) { return x / (1.f + __expf(-x)); }

__device__ __forceinline__ unsigned short bfb(float f) {
    __nv_bfloat16 h = __float2bfloat16(f);
    return *reinterpret_cast<unsigned short*>(&h);
}
__device__ __forceinline__ float bff(__nv_bfloat16 h) { return __bfloat162float(h); }

__device__ __forceinline__ void mma_bf16(float c[4],
                                         unsigned a0, unsigned a1, unsigned a2, unsigned a3,
                                         unsigned b0, unsigned b1)
{
    asm volatile(
        "mma.sync.aligned.m16n8k16.row.col.f32.bf16.bf16.f32 "
        "{%0,%1,%2,%3}, {%4,%5,%6,%7}, {%8,%9}, {%0,%1,%2,%3};"
        : "+f"(c[0]), "+f"(c[1]), "+f"(c[2]), "+f"(c[3])
        : "r"(a0), "r"(a1), "r"(a2), "r"(a3), "r"(b0), "r"(b1));
}

__device__ __forceinline__ void cp16(void* smem, const void* gmem)
{
    unsigned sa = (unsigned)__cvta_generic_to_shared(smem);
    asm volatile("cp.async.cg.shared.global [%0], [%1], 16;" :: "r"(sa), "l"(gmem));
}

__device__ __forceinline__ void ldsm_x4(unsigned& r0, unsigned& r1,
                                        unsigned& r2, unsigned& r3, const void* p)
{
    unsigned a = (unsigned)__cvta_generic_to_shared(p);
    asm volatile("ldmatrix.sync.aligned.m8n8.x4.shared.b16 {%0,%1,%2,%3}, [%4];"
                 : "=r"(r0), "=r"(r1), "=r"(r2), "=r"(r3) : "r"(a));
}

// ---------------------------------------------------------------------
// bf16 GEMM: C = A[M,K] @ W[N,K]^T, m16n8k16 mma, fp32 accum.
// BM=64, BN=64, BK=32. 256 thr = 8 warps (2m x 4n), warp tile 32x16.
// 3-stage cp.async (wait_group 1) + ldmatrix x4 fragments.
// SPLITZ>1: blockIdx.z = K-slice; C -> fp32 partial plane z.
// MODE 0: fp32 store (+n guard)  1: +bias leaky -> fp32
// MODE 2: in_proj split -> bf16 xin/zsil   3: softplus + y (bc from g_bc)
// ---------------------------------------------------------------------
template<int MODE, int SPLITZ>
__global__ void __launch_bounds__(256)
gemm_bf(const __nv_bfloat16* __restrict__ A, int lda,
        const __nv_bfloat16* __restrict__ W, int ldw, int wclamp,
        float* __restrict__ Cf, int N, int K, long cplane,
        const float* __restrict__ aux0,
        const float* __restrict__ aux1,
        __nv_bfloat16* __restrict__ out2)
{
    constexpr int LDSB = 40;           // bf16 units: 80B rows, 16B-aligned, LDSM conflict-free
    __shared__ __align__(16) __nv_bfloat16 As[3][64][LDSB];
    __shared__ __align__(16) __nv_bfloat16 Ws[3][64][LDSB];
    __shared__ float sbc[64];

    const int tid  = threadIdx.x;
    const int lane = tid & 31;
    const int wid  = tid >> 5;
    const int wm   = wid & 1;
    const int wn   = wid >> 1;
    const int g    = lane >> 2;
    const int t    = lane & 3;
    const int m0   = blockIdx.y * 64;
    const int n0   = blockIdx.x * 64;

    const int z = (SPLITZ > 1) ? blockIdx.z : 0;
    const __nv_bfloat16* Az = A + (long)z * K;
    const __nv_bfloat16* Wz = W + (long)z * K;
    float* Cz = Cf + ((SPLITZ > 1) ? (long)z * cplane : 0L);

    const int lrow = tid >> 2;         // 0..63
    const int lc8  = (tid & 3) * 8;    // bf16 col: 0,8,16,24

    const int a_r = lane & 15;
    const int a_c = (lane >> 4) * 8;
    const int b_r = wn * 16 + ((lane >> 4) << 3) + (lane & 7);
    const int b_c = ((lane >> 3) & 1) * 8;

    if (MODE == 3) {                   // stage per-row bc (written by prep_kernel)
        if (tid < 64) sbc[tid] = g_bc[m0 + tid];
    }

    const int NK = K / 32;

    auto load_tiles = [&](int kt, int buf) {
        const int k0 = kt * 32;
        cp16(&As[buf][lrow][lc8], &Az[(long)(m0 + lrow) * lda + k0 + lc8]);
        int wr = n0 + lrow;
        if (wr > wclamp) wr = wclamp;  // dup reads; padded outputs never stored
        cp16(&Ws[buf][lrow][lc8], &Wz[(long)wr * ldw + k0 + lc8]);
    };

    float acc[2][2][4] = {};

    load_tiles(0, 0);
    asm volatile("cp.async.commit_group;");
    if (NK > 1) {
        load_tiles(1, 1);
        asm volatile("cp.async.commit_group;");
    }

    for (int it = 0; it < NK; ++it) {
        if (it + 1 < NK) asm volatile("cp.async.wait_group 1;");
        else             asm volatile("cp.async.wait_group 0;");
        __syncthreads();

        if (it + 2 < NK) {
            load_tiles(it + 2, (it + 2) % 3);
            asm volatile("cp.async.commit_group;");
        }

        const int buf = it % 3;
        #pragma unroll
        for (int ks = 0; ks < 2; ++ks) {
            unsigned b00, b10, b01, b11;
            ldsm_x4(b00, b10, b01, b11, &Ws[buf][b_r][ks*16 + b_c]);
            #pragma unroll
            for (int mt = 0; mt < 2; ++mt) {
                unsigned a0, a1, a2, a3;
                ldsm_x4(a0, a1, a2, a3, &As[buf][wm*32 + mt*16 + a_r][ks*16 + a_c]);
                mma_bf16(acc[mt][0], a0, a1, a2, a3, b00, b10);
                mma_bf16(acc[mt][1], a0, a1, a2, a3, b01, b11);
            }
        }
    }

    // ---- epilogue ----
    #pragma unroll
    for (int mt = 0; mt < 2; ++mt) {
        #pragma unroll
        for (int nt = 0; nt < 2; ++nt) {
            const int nb = n0 + wn*16 + nt*8 + 2*t;
            #pragma unroll
            for (int half = 0; half < 2; ++half) {
                const int m = m0 + wm*32 + mt*16 + g + 8*half;
                float v0 = acc[mt][nt][2*half + 0];
                float v1 = acc[mt][nt][2*half + 1];
                if (MODE == 0) {
                    if (nb < N - 1)
                        *reinterpret_cast<float2*>(&Cz[(long)m*N + nb]) = make_float2(v0, v1);
                } else if (MODE == 1) {
                    v0 += aux0[nb]; v1 += aux0[nb + 1];
                    v0 = (v0 >= 0.f) ? v0 : 0.1f * v0;
                    v1 = (v1 >= 0.f) ? v1 : 0.1f * v1;
                    *reinterpret_cast<float2*>(&Cz[(long)m*N + nb]) = make_float2(v0, v1);
                } else if (MODE == 2) {
                    unsigned pr;
                    if (n0 < DINNER) {      // uniform per CTA (1024 % 64 == 0)
                        float c0 = aux0[nb]     + aux1[2*nb + 1]     * v0;
                        float c1 = aux0[nb + 1] + aux1[2*(nb+1) + 1] * v1;
                        pr = bfb(siluf(c0)) | ((unsigned)bfb(siluf(c1)) << 16);
                        *reinterpret_cast<unsigned*>(&g_xinb[(long)m*DINNER + nb]) = pr;
                    } else {
                        pr = bfb(siluf(v0)) | ((unsigned)bfb(siluf(v1)) << 16);
                        *reinterpret_cast<unsigned*>(&out2[(long)m*DINNER + nb - DINNER]) = pr;
                    }
                } else { // MODE 3
                    v0 += aux0[nb]; v1 += aux0[nb + 1];
                    float dt0 = (v0 > 20.f) ? v0 : log1pf(__expf(v0));
                    float dt1 = (v1 > 20.f) ? v1 : log1pf(__expf(v1));
                    __nv_bfloat162 xv = *reinterpret_cast<const __nv_bfloat162*>(&g_xinb [(long)m*DINNER + nb]);
                    __nv_bfloat162 zv = *reinterpret_cast<const __nv_bfloat162*>(&g_zsilb[(long)m*DINNER + nb]);
                    float bc = sbc[m - m0];
                    float y0 = (dt0 * bff(xv.x) * bc + aux1[nb]     * bff(xv.x)) * bff(zv.x);
                    float y1 = (dt1 * bff(xv.y) * bc + aux1[nb + 1] * bff(xv.y)) * bff(zv.y);
                    unsigned pr = bfb(y0) | ((unsigned)bfb(y1) << 16);
                    *reinterpret_cast<unsigned*>(&g_yb[(long)m*DINNER + nb]) = pr;
                }
            }
        }
    }
}

// ---------------- pre-pass: fp32 -> bf16 for weights + x ----------------
__global__ void convert_kernel(const float* __restrict__ x,
                               const float* __restrict__ win,
                               const float* __restrict__ wxp,
                               const float* __restrict__ wdt,
                               const float* __restrict__ wop,
                               const float* __restrict__ wfc1)
{
    constexpr int S0 = BB*DMODEL/4;
    constexpr int S1 = 2*DINNER*DMODEL/4;
    constexpr int S2 = XDBL_W*DINNER/4;
    constexpr int S3 = DINNER*DTRANK/4;
    constexpr int S4 = DMODEL*DINNER/4;
    constexpr int S5 = HIDDEN*DMODEL/4;
    constexpr int TOT = S0+S1+S2+S3+S4+S5;

    for (int i = blockIdx.x * blockDim.x + threadIdx.x; i < TOT;
         i += gridDim.x * blockDim.x) {
        const float* src; __nv_bfloat16* dst; int j = i;
        if      (j < S0)            { src = x;    dst = b_x; }
        else if ((j -= S0) < S1)    { src = win;  dst = b_win; }
        else if ((j -= S1) < S2)    { src = wxp;  dst = b_wxp; }
        else if ((j -= S2) < S3)    { src = wdt;  dst = b_wdt; }
        else if ((j -= S3) < S4)    { src = wop;  dst = b_wop; }
        else                        { j -= S4;    src = wfc1; dst = b_wfc1; }
        float4 v = reinterpret_cast<const float4*>(src)[j];
        uint2 u;
        u.x = bfb(v.x) | ((unsigned)bfb(v.y) << 16);
        u.y = bfb(v.z) | ((unsigned)bfb(v.w) << 16);
        reinterpret_cast<uint2*>(dst)[j] = u;
    }
}

// ---- prep: per batch row, sum SPLK xdbl planes ONCE -> bc[b] + bf16 dt ----
__global__ void prep_kernel()
{
    const int b = blockIdx.x;          // 512
    const int t = threadIdx.x;         // 128
    const long XP = (long)BB * XDBL_W;
    const long base = (long)b * XDBL_W;

    __shared__ float row[XDBL_W];
    __shared__ float ws[4];

    for (int c = t; c < XDBL_W; c += 128) {
        float s = 0.f;
        #pragma unroll
        for (int p = 0; p < SPLK; ++p) s += g_xdblp[p*XP + base + c];
        row[c] = s;
    }
    __syncthreads();

    // bc = dot(row[32..160), row[160..288)); 128 threads = DSTATE lanes
    float v = row[DTRANK + t] * row[DTRANK + DSTATE + t];
    #pragma unroll
    for (int o = 16; o > 0; o >>= 1) v += __shfl_xor_sync(0xFFFFFFFFu, v, o);
    if ((t & 31) == 0) ws[t >> 5] = v;
    __syncthreads();
    if (t == 0) g_bc[b] = ws[0] + ws[1] + ws[2] + ws[3];
    if (t < DTRANK)
        g_dtb[b*DTRANK + t] = __float2bfloat16(row[t]);
}

// out1_b (bf16) = sum of SPLK fp32 out_proj planes
__global__ void reduce_kernel()
{
    const int i = blockIdx.x * blockDim.x + threadIdx.x;   // 65536 float4s
    const float4* p = reinterpret_cast<const float4*>(g_opart);
    const long plane4 = (long)BB * DMODEL / 4;
    float4 s = p[i];
    #pragma unroll
    for (int z = 1; z < SPLK; ++z) {
        float4 v = p[i + z*plane4];
        s.x += v.x; s.y += v.y; s.z += v.z; s.w += v.w;
    }
    uint2 u;
    u.x = bfb(s.x) | ((unsigned)bfb(s.y) << 16);
    u.y = bfb(s.z) | ((unsigned)bfb(s.w) << 16);
    reinterpret_cast<uint2*>(g_o1b)[i] = u;
}

// out[b] = sigmoid( dot(h1[b], fc5_w) + fc5_b )
__global__ void fc5_kernel(const float* __restrict__ w,
                           const float* __restrict__ bias,
                           float* __restrict__ out)
{
    const int b = blockIdx.x;
    const int t = threadIdx.x;  // 256
    float v = g_h1[b * HIDDEN + t] * w[t];
    #pragma unroll
    for (int o = 16; o > 0; o >>= 1) v += __shfl_xor_sync(0xFFFFFFFFu, v, o);
    __shared__ float ws[8];
    if ((t & 31) == 0) ws[t >> 5] = v;
    __syncthreads();
    if (t == 0) {
        float s = bias[0];
        #pragma unroll
        for (int i = 0; i < 8; i++) s += ws[i];
        out[b] = 1.f / (1.f + __expf(-s));
    }
}

extern "C" void kernel_launch(void* const* d_in, const int* in_sizes, int n_in,
                              void* d_out, int out_size)
{
    const float* x         = (const float*)d_in[0];
    const float* in_proj_w = (const float*)d_in[1];
    const float* conv_w    = (const float*)d_in[2];
    const float* conv_b    = (const float*)d_in[3];
    const float* x_proj_w  = (const float*)d_in[4];
    const float* dt_proj_w = (const float*)d_in[5];
    const float* dt_proj_b = (const float*)d_in[6];
    // d_in[7] = A_log: dead (h0 = 0, L = 1)
    const float* Dp        = (const float*)d_in[8];
    const float* out_projw = (const float*)d_in[9];
    const float* fc1_w     = (const float*)d_in[10];
    const float* fc1_b     = (const float*)d_in[11];
    const float* fc5_w     = (const float*)d_in[12];
    const float* fc5_b     = (const float*)d_in[13];
    float* out = (float*)d_out;

    void *xb, *wib, *wxb, *wdb, *wob, *wfb, *xinb, *zsb, *dtb, *yb, *o1b, *xdp, *opr, *h1;
    cudaGetSymbolAddress(&xb,  b_x);     cudaGetSymbolAddress(&wib, b_win);
    cudaGetSymbolAddress(&wxb, b_wxp);   cudaGetSymbolAddress(&wdb, b_wdt);
    cudaGetSymbolAddress(&wob, b_wop);   cudaGetSymbolAddress(&wfb, b_wfc1);
    cudaGetSymbolAddress(&xinb, g_xinb); cudaGetSymbolAddress(&zsb, g_zsilb);
    cudaGetSymbolAddress(&dtb, g_dtb);   cudaGetSymbolAddress(&yb,  g_yb);
    cudaGetSymbolAddress(&o1b, g_o1b);   cudaGetSymbolAddress(&xdp, g_xdblp);
    cudaGetSymbolAddress(&opr, g_opart); cudaGetSymbolAddress(&h1,  g_h1);

    const long XP = (long)BB * XDBL_W;
    const long OP = (long)BB * DMODEL;
    const dim3 blk(256);

    // 0. fp32 -> bf16 pre-pass (weights + x)
    convert_kernel<<<1024, 256>>>(x, in_proj_w, x_proj_w, dt_proj_w, out_projw, fc1_w);
    // 1. in_proj (N=2048,K=512) + conv + silu split -> bf16 xin,zsil   [256 CTAs]
    gemm_bf<2,1><<<dim3(32, 8), blk>>>((const __nv_bfloat16*)xb, DMODEL,
        (const __nv_bfloat16*)wib, DMODEL, 2*DINNER - 1,
        nullptr, 2*DINNER, DMODEL, 0, conv_b, conv_w, (__nv_bfloat16*)zsb);
    // 2. x_proj split-K x4 (K=256 slices) -> fp32 partials             [160 CTAs]
    gemm_bf<0,SPLK><<<dim3(5, 8, SPLK), blk>>>((const __nv_bfloat16*)xinb, DINNER,
        (const __nv_bfloat16*)wxb, DINNER, XDBL_W - 1,
        (float*)xdp, XDBL_W, DINNER/SPLK, XP, nullptr, nullptr, nullptr);
    // 3. prep: sum planes once -> bc[b] + bf16 dt activations          [512 CTAs]
    prep_kernel<<<BB, 128>>>();
    // 4. dt_proj (K=32, A=bf16 dtb) + softplus + y -> bf16 y           [128 CTAs]
    gemm_bf<3,1><<<dim3(16, 8), blk>>>((const __nv_bfloat16*)dtb, DTRANK,
        (const __nv_bfloat16*)wdb, DTRANK, DINNER - 1,
        nullptr, DINNER, DTRANK, 0, dt_proj_b, Dp, nullptr);
    // 5. out_proj split-K x4 -> fp32 partials                          [256 CTAs]
    gemm_bf<0,SPLK><<<dim3(8, 8, SPLK), blk>>>((const __nv_bfloat16*)yb, DINNER,
        (const __nv_bfloat16*)wob, DINNER, DMODEL - 1,
        (float*)opr, DMODEL, DINNER/SPLK, OP, nullptr, nullptr, nullptr);
    // 6. out1_b = bf16(sum of planes)
    reduce_kernel<<<256, 256>>>();
    // 7. fc1 (N=256,K=512) + bias + leaky -> fp32 h1                   [32 CTAs]
    gemm_bf<1,1><<<dim3(4, 8), blk>>>((const __nv_bfloat16*)o1b, DMODEL,
        (const __nv_bfloat16*)wfb, DMODEL, HIDDEN - 1,
        (float*)h1, HIDDEN, DMODEL, 0, fc1_b, nullptr, nullptr);
    // 8. fc5 + sigmoid -> out (B,1)
    fc5_kernel<<<BB, 256>>>(fc5_w, fc5_b, out);
}

// round 12
// speedup vs baseline: 1.7412x; 1.0035x over previous
#include <cuda_runtime.h>
#include <cuda_bf16.h>
#include <math.h>
#include <stdint.h>

// L = 1 collapses the Mamba scan: h = dBu, y = dt*xin*(Bm.Cm) + D*xin, A_log dead.
#define BB      512
#define DMODEL  512
#define DSTATE  128
#define DINNER  1024
#define DTRANK  32
#define HIDDEN  256
#define XDBL_W  (DTRANK + 2*DSTATE)   // 288
#define SPLK    4

// -------- scratch (no allocations; __device__ globals) --------
__device__ __nv_bfloat16 b_x   [BB*DMODEL];
__device__ __nv_bfloat16 b_win [2*DINNER*DMODEL];
__device__ __nv_bfloat16 b_wxp [XDBL_W*DINNER];
__device__ __nv_bfloat16 b_wdt [DINNER*DTRANK];
__device__ __nv_bfloat16 b_wop [DMODEL*DINNER];
__device__ __nv_bfloat16 b_wfc1[HIDDEN*DMODEL];
__device__ __nv_bfloat16 g_xinb [BB*DINNER];
__device__ __nv_bfloat16 g_zsilb[BB*DINNER];
__device__ __nv_bfloat16 g_dtb  [BB*DTRANK];   // summed dt activations (bf16)
__device__ __nv_bfloat16 g_yb   [BB*DINNER];
__device__ __nv_bfloat16 g_o1b  [BB*DMODEL];
__device__ float g_xdblp[SPLK*BB*XDBL_W];      // x_proj split-K fp32 partials
__device__ float g_opart[SPLK*BB*DMODEL];      // out_proj split-K fp32 partials
__device__ float g_bc   [BB];                  // dot(Bm, Cm) per row
__device__ float g_h1   [BB*HIDDEN];

__device__ __forceinline__ float siluf(float x) { return x / (1.f + __expf(-x)); }

__device__ __forceinline__ unsigned short bfb(float f) {
    __nv_bfloat16 h = __float2bfloat16(f);
    return *reinterpret_cast<unsigned short*>(&h);
}
__device__ __forceinline__ float bff(__nv_bfloat16 h) { return __bfloat162float(h); }

__device__ __forceinline__ void mma_bf16(float c[4],
                                         unsigned a0, unsigned a1, unsigned a2, unsigned a3,
                                         unsigned b0, unsigned b1)
{
    asm volatile(
        "mma.sync.aligned.m16n8k16.row.col.f32.bf16.bf16.f32 "
        "{%0,%1,%2,%3}, {%4,%5,%6,%7}, {%8,%9}, {%0,%1,%2,%3};"
        : "+f"(c[0]), "+f"(c[1]), "+f"(c[2]), "+f"(c[3])
        : "r"(a0), "r"(a1), "r"(a2), "r"(a3), "r"(b0), "r"(b1));
}

__device__ __forceinline__ void cp16(void* smem, const void* gmem)
{
    unsigned sa = (unsigned)__cvta_generic_to_shared(smem);
    asm volatile("cp.async.cg.shared.global [%0], [%1], 16;" :: "r"(sa), "l"(gmem));
}

__device__ __forceinline__ void ldsm_x4(unsigned& r0, unsigned& r1,
                                        unsigned& r2, unsigned& r3, const void* p)
{
    unsigned a = (unsigned)__cvta_generic_to_shared(p);
    asm volatile("ldmatrix.sync.aligned.m8n8.x4.shared.b16 {%0,%1,%2,%3}, [%4];"
                 : "=r"(r0), "=r"(r1), "=r"(r2), "=r"(r3) : "r"(a));
}

// ---------------------------------------------------------------------
// bf16 GEMM: C = A[M,K] @ W[N,K]^T, m16n8k16 mma, fp32 accum.
// BM=64, BN=64, BK=32. 256 thr = 8 warps (2m x 4n), warp tile 32x16.
// 3-stage cp.async (wait_group 1) + ldmatrix x4 fragments.
// SPLITZ>1: blockIdx.z = K-slice; C -> fp32 partial plane z.
// MODE 0: fp32 store (+n guard)  1: +bias leaky -> fp32
// MODE 2: in_proj split -> bf16 xin/zsil   3: softplus + y (bc from g_bc)
// ---------------------------------------------------------------------
template<int MODE, int SPLITZ>
__global__ void __launch_bounds__(256)
gemm_bf(const __nv_bfloat16* __restrict__ A, int lda,
        const __nv_bfloat16* __restrict__ W, int ldw, int wclamp,
        float* __restrict__ Cf, int N, int K, long cplane,
        const float* __restrict__ aux0,
        const float* __restrict__ aux1,
        __nv_bfloat16* __restrict__ out2)
{
    constexpr int LDSB = 40;           // bf16 units: 80B rows, 16B-aligned, LDSM conflict-free
    __shared__ __align__(16) __nv_bfloat16 As[3][64][LDSB];
    __shared__ __align__(16) __nv_bfloat16 Ws[3][64][LDSB];
    __shared__ float sbc[64];

    const int tid  = threadIdx.x;
    const int lane = tid & 31;
    const int wid  = tid >> 5;
    const int wm   = wid & 1;
    const int wn   = wid >> 1;
    const int g    = lane >> 2;
    const int t    = lane & 3;
    const int m0   = blockIdx.y * 64;
    const int n0   = blockIdx.x * 64;

    const int z = (SPLITZ > 1) ? blockIdx.z : 0;
    const __nv_bfloat16* Az = A + (long)z * K;
    const __nv_bfloat16* Wz = W + (long)z * K;
    float* Cz = Cf + ((SPLITZ > 1) ? (long)z * cplane : 0L);

    const int lrow = tid >> 2;         // 0..63
    const int lc8  = (tid & 3) * 8;    // bf16 col: 0,8,16,24

    const int a_r = lane & 15;
    const int a_c = (lane >> 4) * 8;
    const int b_r = wn * 16 + ((lane >> 4) << 3) + (lane & 7);
    const int b_c = ((lane >> 3) & 1) * 8;

    if (MODE == 3) {                   // stage per-row bc (written by prep_kernel)
        if (tid < 64) sbc[tid] = g_bc[m0 + tid];
    }

    const int NK = K / 32;

    auto load_tiles = [&](int kt, int buf) {
        const int k0 = kt * 32;
        cp16(&As[buf][lrow][lc8], &Az[(long)(m0 + lrow) * lda + k0 + lc8]);
        int wr = n0 + lrow;
        if (wr > wclamp) wr = wclamp;  // dup reads; padded outputs never stored
        cp16(&Ws[buf][lrow][lc8], &Wz[(long)wr * ldw + k0 + lc8]);
    };

    float acc[2][2][4] = {};

    load_tiles(0, 0);
    asm volatile("cp.async.commit_group;");
    if (NK > 1) {
        load_tiles(1, 1);
        asm volatile("cp.async.commit_group;");
    }

    for (int it = 0; it < NK; ++it) {
        if (it + 1 < NK) asm volatile("cp.async.wait_group 1;");
        else             asm volatile("cp.async.wait_group 0;");
        __syncthreads();

        if (it + 2 < NK) {
            load_tiles(it + 2, (it + 2) % 3);
            asm volatile("cp.async.commit_group;");
        }

        const int buf = it % 3;
        #pragma unroll
        for (int ks = 0; ks < 2; ++ks) {
            unsigned b00, b10, b01, b11;
            ldsm_x4(b00, b10, b01, b11, &Ws[buf][b_r][ks*16 + b_c]);
            #pragma unroll
            for (int mt = 0; mt < 2; ++mt) {
                unsigned a0, a1, a2, a3;
                ldsm_x4(a0, a1, a2, a3, &As[buf][wm*32 + mt*16 + a_r][ks*16 + a_c]);
                mma_bf16(acc[mt][0], a0, a1, a2, a3, b00, b10);
                mma_bf16(acc[mt][1], a0, a1, a2, a3, b01, b11);
            }
        }
    }

    // ---- epilogue ----
    #pragma unroll
    for (int mt = 0; mt < 2; ++mt) {
        #pragma unroll
        for (int nt = 0; nt < 2; ++nt) {
            const int nb = n0 + wn*16 + nt*8 + 2*t;
            #pragma unroll
            for (int half = 0; half < 2; ++half) {
                const int m = m0 + wm*32 + mt*16 + g + 8*half;
                float v0 = acc[mt][nt][2*half + 0];
                float v1 = acc[mt][nt][2*half + 1];
                if (MODE == 0) {
                    if (nb < N - 1)
                        *reinterpret_cast<float2*>(&Cz[(long)m*N + nb]) = make_float2(v0, v1);
                } else if (MODE == 1) {
                    v0 += aux0[nb]; v1 += aux0[nb + 1];
                    v0 = (v0 >= 0.f) ? v0 : 0.1f * v0;
                    v1 = (v1 >= 0.f) ? v1 : 0.1f * v1;
                    *reinterpret_cast<float2*>(&Cz[(long)m*N + nb]) = make_float2(v0, v1);
                } else if (MODE == 2) {
                    unsigned pr;
                    if (n0 < DINNER) {      // uniform per CTA (1024 % 64 == 0)
                        float c0 = aux0[nb]     + aux1[2*nb + 1]     * v0;
                        float c1 = aux0[nb + 1] + aux1[2*(nb+1) + 1] * v1;
                        pr = bfb(siluf(c0)) | ((unsigned)bfb(siluf(c1)) << 16);
                        *reinterpret_cast<unsigned*>(&g_xinb[(long)m*DINNER + nb]) = pr;
                    } else {
                        pr = bfb(siluf(v0)) | ((unsigned)bfb(siluf(v1)) << 16);
                        *reinterpret_cast<unsigned*>(&out2[(long)m*DINNER + nb - DINNER]) = pr;
                    }
                } else { // MODE 3
                    v0 += aux0[nb]; v1 += aux0[nb + 1];
                    float dt0 = (v0 > 20.f) ? v0 : log1pf(__expf(v0));
                    float dt1 = (v1 > 20.f) ? v1 : log1pf(__expf(v1));
                    __nv_bfloat162 xv = *reinterpret_cast<const __nv_bfloat162*>(&g_xinb [(long)m*DINNER + nb]);
                    __nv_bfloat162 zv = *reinterpret_cast<const __nv_bfloat162*>(&g_zsilb[(long)m*DINNER + nb]);
                    float bc = sbc[m - m0];
                    float y0 = (dt0 * bff(xv.x) * bc + aux1[nb]     * bff(xv.x)) * bff(zv.x);
                    float y1 = (dt1 * bff(xv.y) * bc + aux1[nb + 1] * bff(xv.y)) * bff(zv.y);
                    unsigned pr = bfb(y0) | ((unsigned)bfb(y1) << 16);
                    *reinterpret_cast<unsigned*>(&g_yb[(long)m*DINNER + nb]) = pr;
                }
            }
        }
    }
}

// ---------------- pre-pass: fp32 -> bf16 for weights + x ----------------
__global__ void convert_kernel(const float* __restrict__ x,
                               const float* __restrict__ win,
                               const float* __restrict__ wxp,
                               const float* __restrict__ wdt,
                               const float* __restrict__ wop,
                               const float* __restrict__ wfc1)
{
    constexpr int S0 = BB*DMODEL/4;
    constexpr int S1 = 2*DINNER*DMODEL/4;
    constexpr int S2 = XDBL_W*DINNER/4;
    constexpr int S3 = DINNER*DTRANK/4;
    constexpr int S4 = DMODEL*DINNER/4;
    constexpr int S5 = HIDDEN*DMODEL/4;
    constexpr int TOT = S0+S1+S2+S3+S4+S5;

    for (int i = blockIdx.x * blockDim.x + threadIdx.x; i < TOT;
         i += gridDim.x * blockDim.x) {
        const float* src; __nv_bfloat16* dst; int j = i;
        if      (j < S0)            { src = x;    dst = b_x; }
        else if ((j -= S0) < S1)    { src = win;  dst = b_win; }
        else if ((j -= S1) < S2)    { src = wxp;  dst = b_wxp; }
        else if ((j -= S2) < S3)    { src = wdt;  dst = b_wdt; }
        else if ((j -= S3) < S4)    { src = wop;  dst = b_wop; }
        else                        { j -= S4;    src = wfc1; dst = b_wfc1; }
        float4 v = reinterpret_cast<const float4*>(src)[j];
        uint2 u;
        u.x = bfb(v.x) | ((unsigned)bfb(v.y) << 16);
        u.y = bfb(v.z) | ((unsigned)bfb(v.w) << 16);
        reinterpret_cast<uint2*>(dst)[j] = u;
    }
}

// ---- prep: sum SPLK xdbl planes once -> bc[b] + bf16 dt activations ----
// grid 64 CTAs x 256 thr; CTA handles 8 rows; one warp per row for bc/dt.
__global__ void __launch_bounds__(256) prep_kernel()
{
    const int b0  = blockIdx.x * 8;
    const int tid = threadIdx.x;
    const int w   = tid >> 5;
    const int lane = tid & 31;
    const long XP = (long)BB * XDBL_W;

    __shared__ float rows[8][XDBL_W];

    // cooperative coalesced load+sum: 8*288 = 2304 elems, 9 per thread
    #pragma unroll
    for (int i = tid; i < 8 * XDBL_W; i += 256) {
        const int r = i / XDBL_W, c = i - r * XDBL_W;
        const long base = (long)(b0 + r) * XDBL_W + c;
        float s = g_xdblp[base];
        #pragma unroll
        for (int p = 1; p < SPLK; ++p) s += g_xdblp[p*XP + base];
        rows[r][c] = s;
    }
    __syncthreads();

    // warp w owns row w: bc = dot(Bm, Cm), 4 elems per lane
    float v = 0.f;
    #pragma unroll
    for (int i = 0; i < DSTATE / 32; ++i) {
        const int c = lane + 32*i;
        v += rows[w][DTRANK + c] * rows[w][DTRANK + DSTATE + c];
    }
    #pragma unroll
    for (int o = 16; o > 0; o >>= 1) v += __shfl_xor_sync(0xFFFFFFFFu, v, o);
    if (lane == 0) g_bc[b0 + w] = v;
    // dt activations: 32 lanes = DTRANK cols
    g_dtb[(b0 + w)*DTRANK + lane] = __float2bfloat16(rows[w][lane]);
}

// out1_b (bf16) = sum of SPLK fp32 out_proj planes
__global__ void reduce_kernel()
{
    const int i = blockIdx.x * blockDim.x + threadIdx.x;   // 65536 float4s
    const float4* p = reinterpret_cast<const float4*>(g_opart);
    const long plane4 = (long)BB * DMODEL / 4;
    float4 s = p[i];
    #pragma unroll
    for (int z = 1; z < SPLK; ++z) {
        float4 v = p[i + z*plane4];
        s.x += v.x; s.y += v.y; s.z += v.z; s.w += v.w;
    }
    uint2 u;
    u.x = bfb(s.x) | ((unsigned)bfb(s.y) << 16);
    u.y = bfb(s.z) | ((unsigned)bfb(s.w) << 16);
    reinterpret_cast<uint2*>(g_o1b)[i] = u;
}

// out[b] = sigmoid( dot(h1[b], fc5_w) + fc5_b ); one warp per row
__global__ void __launch_bounds__(256) fc5_kernel(const float* __restrict__ w,
                                                  const float* __restrict__ bias,
                                                  float* __restrict__ out)
{
    const int wd   = threadIdx.x >> 5;
    const int lane = threadIdx.x & 31;
    const int b    = blockIdx.x * 8 + wd;          // grid 64

    const float4* h  = reinterpret_cast<const float4*>(&g_h1[b * HIDDEN]);
    const float4* wf = reinterpret_cast<const float4*>(w);
    float v = 0.f;
    #pragma unroll
    for (int i = 0; i < HIDDEN / 128; ++i) {       // 2 float4 per lane
        float4 a = h[lane + 32*i], c = wf[lane + 32*i];
        v += a.x*c.x + a.y*c.y + a.z*c.z + a.w*c.w;
    }
    #pragma unroll
    for (int o = 16; o > 0; o >>= 1) v += __shfl_xor_sync(0xFFFFFFFFu, v, o);
    if (lane == 0)
        out[b] = 1.f / (1.f + __expf(-(v + bias[0])));
}

extern "C" void kernel_launch(void* const* d_in, const int* in_sizes, int n_in,
                              void* d_out, int out_size)
{
    const float* x         = (const float*)d_in[0];
    const float* in_proj_w = (const float*)d_in[1];
    const float* conv_w    = (const float*)d_in[2];
    const float* conv_b    = (const float*)d_in[3];
    const float* x_proj_w  = (const float*)d_in[4];
    const float* dt_proj_w = (const float*)d_in[5];
    const float* dt_proj_b = (const float*)d_in[6];
    // d_in[7] = A_log: dead (h0 = 0, L = 1)
    const float* Dp        = (const float*)d_in[8];
    const float* out_projw = (const float*)d_in[9];
    const float* fc1_w     = (const float*)d_in[10];
    const float* fc1_b     = (const float*)d_in[11];
    const float* fc5_w     = (const float*)d_in[12];
    const float* fc5_b     = (const float*)d_in[13];
    float* out = (float*)d_out;

    void *xb, *wib, *wxb, *wdb, *wob, *wfb, *xinb, *zsb, *dtb, *yb, *o1b, *xdp, *opr, *h1;
    cudaGetSymbolAddress(&xb,  b_x);     cudaGetSymbolAddress(&wib, b_win);
    cudaGetSymbolAddress(&wxb, b_wxp);   cudaGetSymbolAddress(&wdb, b_wdt);
    cudaGetSymbolAddress(&wob, b_wop);   cudaGetSymbolAddress(&wfb, b_wfc1);
    cudaGetSymbolAddress(&xinb, g_xinb); cudaGetSymbolAddress(&zsb, g_zsilb);
    cudaGetSymbolAddress(&dtb, g_dtb);   cudaGetSymbolAddress(&yb,  g_yb);
    cudaGetSymbolAddress(&o1b, g_o1b);   cudaGetSymbolAddress(&xdp, g_xdblp);
    cudaGetSymbolAddress(&opr, g_opart); cudaGetSymbolAddress(&h1,  g_h1);

    const long XP = (long)BB * XDBL_W;
    const long OP = (long)BB * DMODEL;
    const dim3 blk(256);

    // 0. fp32 -> bf16 pre-pass (weights + x)
    convert_kernel<<<1024, 256>>>(x, in_proj_w, x_proj_w, dt_proj_w, out_projw, fc1_w);
    // 1. in_proj (N=2048,K=512) + conv + silu split -> bf16 xin,zsil   [256 CTAs]
    gemm_bf<2,1><<<dim3(32, 8), blk>>>((const __nv_bfloat16*)xb, DMODEL,
        (const __nv_bfloat16*)wib, DMODEL, 2*DINNER - 1,
        nullptr, 2*DINNER, DMODEL, 0, conv_b, conv_w, (__nv_bfloat16*)zsb);
    // 2. x_proj split-K x4 (K=256 slices) -> fp32 partials             [160 CTAs]
    gemm_bf<0,SPLK><<<dim3(5, 8, SPLK), blk>>>((const __nv_bfloat16*)xinb, DINNER,
        (const __nv_bfloat16*)wxb, DINNER, XDBL_W - 1,
        (float*)xdp, XDBL_W, DINNER/SPLK, XP, nullptr, nullptr, nullptr);
    // 3. prep: sum planes once -> bc[b] + bf16 dt activations          [64 CTAs]
    prep_kernel<<<BB/8, 256>>>();
    // 4. dt_proj (K=32, A=bf16 dtb) + softplus + y -> bf16 y           [128 CTAs]
    gemm_bf<3,1><<<dim3(16, 8), blk>>>((const __nv_bfloat16*)dtb, DTRANK,
        (const __nv_bfloat16*)wdb, DTRANK, DINNER - 1,
        nullptr, DINNER, DTRANK, 0, dt_proj_b, Dp, nullptr);
    // 5. out_proj split-K x4 -> fp32 partials                          [256 CTAs]
    gemm_bf<0,SPLK><<<dim3(8, 8, SPLK), blk>>>((const __nv_bfloat16*)yb, DINNER,
        (const __nv_bfloat16*)wob, DINNER, DMODEL - 1,
        (float*)opr, DMODEL, DINNER/SPLK, OP, nullptr, nullptr, nullptr);
    // 6. out1_b = bf16(sum of planes)
    reduce_kernel<<<256, 256>>>();
    // 7. fc1 (N=256,K=512) + bias + leaky -> fp32 h1                   [32 CTAs]
    gemm_bf<1,1><<<dim3(4, 8), blk>>>((const __nv_bfloat16*)o1b, DMODEL,
        (const __nv_bfloat16*)wfb, DMODEL, HIDDEN - 1,
        (float*)h1, HIDDEN, DMODEL, 0, fc1_b, nullptr, nullptr);
    // 8. fc5 + sigmoid -> out (B,1)
    fc5_kernel<<<BB/8, 256>>>(fc5_w, fc5_b, out);
}

// round 13
// speedup vs baseline: 1.7437x; 1.0014x over previous
#include <cuda_runtime.h>
#include <cuda_bf16.h>
#include <math.h>
#include <stdint.h>

// L = 1 collapses the Mamba scan: h = dBu, y = dt*xin*(Bm.Cm) + D*xin, A_log dead.
#define BB      512
#define DMODEL  512
#define DSTATE  128
#define DINNER  1024
#define DTRANK  32
#define HIDDEN  256
#define XDBL_W  (DTRANK + 2*DSTATE)   // 288
#define SPLK    4

// -------- scratch (no allocations; __device__ globals) --------
__device__ __nv_bfloat16 b_x   [BB*DMODEL];
__device__ __nv_bfloat16 b_win [2*DINNER*DMODEL];
__device__ __nv_bfloat16 b_wxp [XDBL_W*DINNER];
__device__ __nv_bfloat16 b_wdt [DINNER*DTRANK];
__device__ __nv_bfloat16 b_wop [DMODEL*DINNER];
__device__ __nv_bfloat16 b_wfc1[HIDDEN*DMODEL];
__device__ __nv_bfloat16 g_xinb [BB*DINNER];
__device__ __nv_bfloat16 g_zsilb[BB*DINNER];
__device__ __nv_bfloat16 g_dtb  [BB*DTRANK];   // summed dt activations (bf16)
__device__ __nv_bfloat16 g_yb   [BB*DINNER];
__device__ __nv_bfloat16 g_o1b  [BB*DMODEL];
__device__ float g_xdblp[SPLK*BB*XDBL_W];      // x_proj split-K fp32 partials
__device__ float g_xdbls[BB*XDBL_W];           // summed xdbl (fp32)
__device__ float g_opart[SPLK*BB*DMODEL];      // out_proj split-K fp32 partials
__device__ float g_bc   [BB];                  // dot(Bm, Cm) per row
__device__ float g_h1   [BB*HIDDEN];

__device__ __forceinline__ float siluf(float x) { return x / (1.f + __expf(-x)); }

__device__ __forceinline__ unsigned short bfb(float f) {
    __nv_bfloat16 h = __float2bfloat16(f);
    return *reinterpret_cast<unsigned short*>(&h);
}
__device__ __forceinline__ float bff(__nv_bfloat16 h) { return __bfloat162float(h); }

__device__ __forceinline__ void mma_bf16(float c[4],
                                         unsigned a0, unsigned a1, unsigned a2, unsigned a3,
                                         unsigned b0, unsigned b1)
{
    asm volatile(
        "mma.sync.aligned.m16n8k16.row.col.f32.bf16.bf16.f32 "
        "{%0,%1,%2,%3}, {%4,%5,%6,%7}, {%8,%9}, {%0,%1,%2,%3};"
        : "+f"(c[0]), "+f"(c[1]), "+f"(c[2]), "+f"(c[3])
        : "r"(a0), "r"(a1), "r"(a2), "r"(a3), "r"(b0), "r"(b1));
}

__device__ __forceinline__ void cp16(void* smem, const void* gmem)
{
    unsigned sa = (unsigned)__cvta_generic_to_shared(smem);
    asm volatile("cp.async.cg.shared.global [%0], [%1], 16;" :: "r"(sa), "l"(gmem));
}

__device__ __forceinline__ void ldsm_x4(unsigned& r0, unsigned& r1,
                                        unsigned& r2, unsigned& r3, const void* p)
{
    unsigned a = (unsigned)__cvta_generic_to_shared(p);
    asm volatile("ldmatrix.sync.aligned.m8n8.x4.shared.b16 {%0,%1,%2,%3}, [%4];"
                 : "=r"(r0), "=r"(r1), "=r"(r2), "=r"(r3) : "r"(a));
}

// ---------------------------------------------------------------------
// bf16 GEMM: C = A[M,K] @ W[N,K]^T, m16n8k16 mma, fp32 accum.
// BM=64, BN=64, BK=32. 256 thr = 8 warps (2m x 4n), warp tile 32x16.
// 3-stage cp.async (wait_group 1) + ldmatrix x4 fragments.
// SPLITZ>1: blockIdx.z = K-slice; C -> fp32 partial plane z.
// MODE 0: fp32 store (+n guard)  1: +bias leaky -> fp32
// MODE 2: in_proj split -> bf16 xin/zsil   3: softplus + y (bc from g_bc)
// ---------------------------------------------------------------------
template<int MODE, int SPLITZ>
__global__ void __launch_bounds__(256)
gemm_bf(const __nv_bfloat16* __restrict__ A, int lda,
        const __nv_bfloat16* __restrict__ W, int ldw, int wclamp,
        float* __restrict__ Cf, int N, int K, long cplane,
        const float* __restrict__ aux0,
        const float* __restrict__ aux1,
        __nv_bfloat16* __restrict__ out2)
{
    constexpr int LDSB = 40;           // bf16 units: 80B rows, 16B-aligned, LDSM conflict-free
    __shared__ __align__(16) __nv_bfloat16 As[3][64][LDSB];
    __shared__ __align__(16) __nv_bfloat16 Ws[3][64][LDSB];
    __shared__ float sbc[64];

    const int tid  = threadIdx.x;
    const int lane = tid & 31;
    const int wid  = tid >> 5;
    const int wm   = wid & 1;
    const int wn   = wid >> 1;
    const int g    = lane >> 2;
    const int t    = lane & 3;
    const int m0   = blockIdx.y * 64;
    const int n0   = blockIdx.x * 64;

    const int z = (SPLITZ > 1) ? blockIdx.z : 0;
    const __nv_bfloat16* Az = A + (long)z * K;
    const __nv_bfloat16* Wz = W + (long)z * K;
    float* Cz = Cf + ((SPLITZ > 1) ? (long)z * cplane : 0L);

    const int lrow = tid >> 2;         // 0..63
    const int lc8  = (tid & 3) * 8;    // bf16 col: 0,8,16,24

    const int a_r = lane & 15;
    const int a_c = (lane >> 4) * 8;
    const int b_r = wn * 16 + ((lane >> 4) << 3) + (lane & 7);
    const int b_c = ((lane >> 3) & 1) * 8;

    if (MODE == 3) {                   // stage per-row bc (written by bc_kernel)
        if (tid < 64) sbc[tid] = g_bc[m0 + tid];
    }

    const int NK = K / 32;

    auto load_tiles = [&](int kt, int buf) {
        const int k0 = kt * 32;
        cp16(&As[buf][lrow][lc8], &Az[(long)(m0 + lrow) * lda + k0 + lc8]);
        int wr = n0 + lrow;
        if (wr > wclamp) wr = wclamp;  // dup reads; padded outputs never stored
        cp16(&Ws[buf][lrow][lc8], &Wz[(long)wr * ldw + k0 + lc8]);
    };

    float acc[2][2][4] = {};

    load_tiles(0, 0);
    asm volatile("cp.async.commit_group;");
    if (NK > 1) {
        load_tiles(1, 1);
        asm volatile("cp.async.commit_group;");
    }

    for (int it = 0; it < NK; ++it) {
        if (it + 1 < NK) asm volatile("cp.async.wait_group 1;");
        else             asm volatile("cp.async.wait_group 0;");
        __syncthreads();

        if (it + 2 < NK) {
            load_tiles(it + 2, (it + 2) % 3);
            asm volatile("cp.async.commit_group;");
        }

        const int buf = it % 3;
        #pragma unroll
        for (int ks = 0; ks < 2; ++ks) {
            unsigned b00, b10, b01, b11;
            ldsm_x4(b00, b10, b01, b11, &Ws[buf][b_r][ks*16 + b_c]);
            #pragma unroll
            for (int mt = 0; mt < 2; ++mt) {
                unsigned a0, a1, a2, a3;
                ldsm_x4(a0, a1, a2, a3, &As[buf][wm*32 + mt*16 + a_r][ks*16 + a_c]);
                mma_bf16(acc[mt][0], a0, a1, a2, a3, b00, b10);
                mma_bf16(acc[mt][1], a0, a1, a2, a3, b01, b11);
            }
        }
    }

    // ---- epilogue ----
    #pragma unroll
    for (int mt = 0; mt < 2; ++mt) {
        #pragma unroll
        for (int nt = 0; nt < 2; ++nt) {
            const int nb = n0 + wn*16 + nt*8 + 2*t;
            #pragma unroll
            for (int half = 0; half < 2; ++half) {
                const int m = m0 + wm*32 + mt*16 + g + 8*half;
                float v0 = acc[mt][nt][2*half + 0];
                float v1 = acc[mt][nt][2*half + 1];
                if (MODE == 0) {
                    if (nb < N - 1)
                        *reinterpret_cast<float2*>(&Cz[(long)m*N + nb]) = make_float2(v0, v1);
                } else if (MODE == 1) {
                    v0 += aux0[nb]; v1 += aux0[nb + 1];
                    v0 = (v0 >= 0.f) ? v0 : 0.1f * v0;
                    v1 = (v1 >= 0.f) ? v1 : 0.1f * v1;
                    *reinterpret_cast<float2*>(&Cz[(long)m*N + nb]) = make_float2(v0, v1);
                } else if (MODE == 2) {
                    unsigned pr;
                    if (n0 < DINNER) {      // uniform per CTA (1024 % 64 == 0)
                        float c0 = aux0[nb]     + aux1[2*nb + 1]     * v0;
                        float c1 = aux0[nb + 1] + aux1[2*(nb+1) + 1] * v1;
                        pr = bfb(siluf(c0)) | ((unsigned)bfb(siluf(c1)) << 16);
                        *reinterpret_cast<unsigned*>(&g_xinb[(long)m*DINNER + nb]) = pr;
                    } else {
                        pr = bfb(siluf(v0)) | ((unsigned)bfb(siluf(v1)) << 16);
                        *reinterpret_cast<unsigned*>(&out2[(long)m*DINNER + nb - DINNER]) = pr;
                    }
                } else { // MODE 3
                    v0 += aux0[nb]; v1 += aux0[nb + 1];
                    float dt0 = (v0 > 20.f) ? v0 : log1pf(__expf(v0));
                    float dt1 = (v1 > 20.f) ? v1 : log1pf(__expf(v1));
                    __nv_bfloat162 xv = *reinterpret_cast<const __nv_bfloat162*>(&g_xinb [(long)m*DINNER + nb]);
                    __nv_bfloat162 zv = *reinterpret_cast<const __nv_bfloat162*>(&g_zsilb[(long)m*DINNER + nb]);
                    float bc = sbc[m - m0];
                    float y0 = (dt0 * bff(xv.x) * bc + aux1[nb]     * bff(xv.x)) * bff(zv.x);
                    float y1 = (dt1 * bff(xv.y) * bc + aux1[nb + 1] * bff(xv.y)) * bff(zv.y);
                    unsigned pr = bfb(y0) | ((unsigned)bfb(y1) << 16);
                    *reinterpret_cast<unsigned*>(&g_yb[(long)m*DINNER + nb]) = pr;
                }
            }
        }
    }
}

// ---------------- pre-pass: fp32 -> bf16 for weights + x ----------------
__global__ void convert_kernel(const float* __restrict__ x,
                               const float* __restrict__ win,
                               const float* __restrict__ wxp,
                               const float* __restrict__ wdt,
                               const float* __restrict__ wop,
                               const float* __restrict__ wfc1)
{
    constexpr int S0 = BB*DMODEL/4;
    constexpr int S1 = 2*DINNER*DMODEL/4;
    constexpr int S2 = XDBL_W*DINNER/4;
    constexpr int S3 = DINNER*DTRANK/4;
    constexpr int S4 = DMODEL*DINNER/4;
    constexpr int S5 = HIDDEN*DMODEL/4;
    constexpr int TOT = S0+S1+S2+S3+S4+S5;

    for (int i = blockIdx.x * blockDim.x + threadIdx.x; i < TOT;
         i += gridDim.x * blockDim.x) {
        const float* src; __nv_bfloat16* dst; int j = i;
        if      (j < S0)            { src = x;    dst = b_x; }
        else if ((j -= S0) < S1)    { src = win;  dst = b_win; }
        else if ((j -= S1) < S2)    { src = wxp;  dst = b_wxp; }
        else if ((j -= S2) < S3)    { src = wdt;  dst = b_wdt; }
        else if ((j -= S3) < S4)    { src = wop;  dst = b_wop; }
        else                        { j -= S4;    src = wfc1; dst = b_wfc1; }
        float4 v = reinterpret_cast<const float4*>(src)[j];
        uint2 u;
        u.x = bfb(v.x) | ((unsigned)bfb(v.y) << 16);
        u.y = bfb(v.z) | ((unsigned)bfb(v.w) << 16);
        reinterpret_cast<uint2*>(dst)[j] = u;
    }
}

// ---- flat float4 sum of SPLK xdbl planes -> g_xdbls (+ bf16 dt cols) ----
// grid 144 x 256: one float4 per thread (512*288/4 = 36864).
__global__ void __launch_bounds__(256) sum_xdbl_kernel()
{
    const int i = blockIdx.x * 256 + threadIdx.x;
    const long plane4 = (long)BB * XDBL_W / 4;     // 36864
    const float4* p = reinterpret_cast<const float4*>(g_xdblp);
    float4 s = p[i];
    #pragma unroll
    for (int z = 1; z < SPLK; ++z) {
        float4 v = p[i + z*plane4];
        s.x += v.x; s.y += v.y; s.z += v.z; s.w += v.w;
    }
    reinterpret_cast<float4*>(g_xdbls)[i] = s;

    const int c = (i % (XDBL_W/4)) * 4;            // 72 float4 per row
    if (c < DTRANK) {
        const int r = i / (XDBL_W/4);
        uint2 u;
        u.x = bfb(s.x) | ((unsigned)bfb(s.y) << 16);
        u.y = bfb(s.z) | ((unsigned)bfb(s.w) << 16);
        *reinterpret_cast<uint2*>(&g_dtb[r*DTRANK + c]) = u;
    }
}

// ---- bc[b] = dot(Bm, Cm) of summed row; one warp per row, float4 lanes ----
__global__ void __launch_bounds__(256) bc_kernel()
{
    const int w    = threadIdx.x >> 5;
    const int lane = threadIdx.x & 31;
    const int b    = blockIdx.x * 8 + w;           // grid 64
    const float4* row4 = reinterpret_cast<const float4*>(&g_xdbls[(long)b * XDBL_W]);
    // Bm: float idx 32..159 = float4 8..39 ; Cm: 160..287 = float4 40..71
    float4 a = row4[8 + lane], c = row4[40 + lane];
    float v = a.x*c.x + a.y*c.y + a.z*c.z + a.w*c.w;
    #pragma unroll
    for (int o = 16; o > 0; o >>= 1) v += __shfl_xor_sync(0xFFFFFFFFu, v, o);
    if (lane == 0) g_bc[b] = v;
}

// out1_b (bf16) = sum of SPLK fp32 out_proj planes
__global__ void reduce_kernel()
{
    const int i = blockIdx.x * blockDim.x + threadIdx.x;   // 65536 float4s
    const float4* p = reinterpret_cast<const float4*>(g_opart);
    const long plane4 = (long)BB * DMODEL / 4;
    float4 s = p[i];
    #pragma unroll
    for (int z = 1; z < SPLK; ++z) {
        float4 v = p[i + z*plane4];
        s.x += v.x; s.y += v.y; s.z += v.z; s.w += v.w;
    }
    uint2 u;
    u.x = bfb(s.x) | ((unsigned)bfb(s.y) << 16);
    u.y = bfb(s.z) | ((unsigned)bfb(s.w) << 16);
    reinterpret_cast<uint2*>(g_o1b)[i] = u;
}

// out[b] = sigmoid( dot(h1[b], fc5_w) + fc5_b ); one warp per row
__global__ void __launch_bounds__(256) fc5_kernel(const float* __restrict__ w,
                                                  const float* __restrict__ bias,
                                                  float* __restrict__ out)
{
    const int wd   = threadIdx.x >> 5;
    const int lane = threadIdx.x & 31;
    const int b    = blockIdx.x * 8 + wd;          // grid 64

    const float4* h  = reinterpret_cast<const float4*>(&g_h1[b * HIDDEN]);
    const float4* wf = reinterpret_cast<const float4*>(w);
    float v = 0.f;
    #pragma unroll
    for (int i = 0; i < HIDDEN / 128; ++i) {       // 2 float4 per lane
        float4 a = h[lane + 32*i], c = wf[lane + 32*i];
        v += a.x*c.x + a.y*c.y + a.z*c.z + a.w*c.w;
    }
    #pragma unroll
    for (int o = 16; o > 0; o >>= 1) v += __shfl_xor_sync(0xFFFFFFFFu, v, o);
    if (lane == 0)
        out[b] = 1.f / (1.f + __expf(-(v + bias[0])));
}

extern "C" void kernel_launch(void* const* d_in, const int* in_sizes, int n_in,
                              void* d_out, int out_size)
{
    const float* x         = (const float*)d_in[0];
    const float* in_proj_w = (const float*)d_in[1];
    const float* conv_w    = (const float*)d_in[2];
    const float* conv_b    = (const float*)d_in[3];
    const float* x_proj_w  = (const float*)d_in[4];
    const float* dt_proj_w = (const float*)d_in[5];
    const float* dt_proj_b = (const float*)d_in[6];
    // d_in[7] = A_log: dead (h0 = 0, L = 1)
    const float* Dp        = (const float*)d_in[8];
    const float* out_projw = (const float*)d_in[9];
    const float* fc1_w     = (const float*)d_in[10];
    const float* fc1_b     = (const float*)d_in[11];
    const float* fc5_w     = (const float*)d_in[12];
    const float* fc5_b     = (const float*)d_in[13];
    float* out = (float*)d_out;

    void *xb, *wib, *wxb, *wdb, *wob, *wfb, *dtb, *yb, *o1b, *xdp, *opr, *h1;
    cudaGetSymbolAddress(&xb,  b_x);     cudaGetSymbolAddress(&wib, b_win);
    cudaGetSymbolAddress(&wxb, b_wxp);   cudaGetSymbolAddress(&wdb, b_wdt);
    cudaGetSymbolAddress(&wob, b_wop);   cudaGetSymbolAddress(&wfb, b_wfc1);
    cudaGetSymbolAddress(&dtb, g_dtb);   cudaGetSymbolAddress(&yb,  g_yb);
    cudaGetSymbolAddress(&o1b, g_o1b);   cudaGetSymbolAddress(&xdp, g_xdblp);
    cudaGetSymbolAddress(&opr, g_opart); cudaGetSymbolAddress(&h1,  g_h1);
    void *zsb;
    cudaGetSymbolAddress(&zsb, g_zsilb);

    const long XP = (long)BB * XDBL_W;
    const long OP = (long)BB * DMODEL;
    const dim3 blk(256);

    // 0. fp32 -> bf16 pre-pass (weights + x)
    convert_kernel<<<1024, 256>>>(x, in_proj_w, x_proj_w, dt_proj_w, out_projw, fc1_w);
    // 1. in_proj (N=2048,K=512) + conv + silu split -> bf16 xin,zsil   [256 CTAs]
    gemm_bf<2,1><<<dim3(32, 8), blk>>>((const __nv_bfloat16*)xb, DMODEL,
        (const __nv_bfloat16*)wib, DMODEL, 2*DINNER - 1,
        nullptr, 2*DINNER, DMODEL, 0, conv_b, conv_w, (__nv_bfloat16*)zsb);
    // 2. x_proj split-K x4 (K=256 slices) -> fp32 partials             [160 CTAs]
    {
        void* xinb; cudaGetSymbolAddress(&xinb, g_xinb);
        gemm_bf<0,SPLK><<<dim3(5, 8, SPLK), blk>>>((const __nv_bfloat16*)xinb, DINNER,
            (const __nv_bfloat16*)wxb, DINNER, XDBL_W - 1,
            (float*)xdp, XDBL_W, DINNER/SPLK, XP, nullptr, nullptr, nullptr);
    }
    // 3a. flat plane sum -> g_xdbls + bf16 dt                          [144 CTAs]
    sum_xdbl_kernel<<<(BB*XDBL_W/4)/256, 256>>>();
    // 3b. bc[b] from summed rows                                      [64 CTAs]
    bc_kernel<<<BB/8, 256>>>();
    // 4. dt_proj (K=32, A=bf16 dtb) + softplus + y -> bf16 y           [128 CTAs]
    gemm_bf<3,1><<<dim3(16, 8), blk>>>((const __nv_bfloat16*)dtb, DTRANK,
        (const __nv_bfloat16*)wdb, DTRANK, DINNER - 1,
        nullptr, DINNER, DTRANK, 0, dt_proj_b, Dp, nullptr);
    // 5. out_proj split-K x4 -> fp32 partials                          [256 CTAs]
    gemm_bf<0,SPLK><<<dim3(8, 8, SPLK), blk>>>((const __nv_bfloat16*)yb, DINNER,
        (const __nv_bfloat16*)wob, DINNER, DMODEL - 1,
        (float*)opr, DMODEL, DINNER/SPLK, OP, nullptr, nullptr, nullptr);
    // 6. out1_b = bf16(sum of planes)
    reduce_kernel<<<256, 256>>>();
    // 7. fc1 (N=256,K=512) + bias + leaky -> fp32 h1                   [32 CTAs]
    gemm_bf<1,1><<<dim3(4, 8), blk>>>((const __nv_bfloat16*)o1b, DMODEL,
        (const __nv_bfloat16*)wfb, DMODEL, HIDDEN - 1,
        (float*)h1, HIDDEN, DMODEL, 0, fc1_b, nullptr, nullptr);
    // 8. fc5 + sigmoid -> out (B,1)
    fc5_kernel<<<BB/8, 256>>>(fc5_w, fc5_b, out);
}